// round 7
// baseline (speedup 1.0000x reference)
#include <cuda_runtime.h>
#include <cuda_bf16.h>
#include <cstdint>
#include <math.h>

// Problem constants
#define B_   4
#define LQ_  8192
#define S_   16384
#define D_   256
#define NH_  8
#define NP_  4
#define DH_  32
#define HH_  128
#define WW_  128
#define NQ_  (B_ * LQ_)   // 32768
#define NS_  (B_ * S_)    // 65536

// ---------------- scratch (static __device__ — no allocations) ----------------
__device__ float g_value[(size_t)NS_ * D_];       // 64 MB
__device__ float g_offattn[(size_t)NQ_ * 96];     // 12 MB
__device__ float g_sampled[(size_t)NQ_ * D_];     // 32 MB
__device__ float g_Woa[256 * 96];
__device__ float g_boa[96];

// ---------------- pack W_off | W_attn into one [256,96] weight ----------------
__global__ void pack_w_kernel(const float* __restrict__ Woff, const float* __restrict__ boff,
                              const float* __restrict__ Wattn, const float* __restrict__ battn) {
    int i = blockIdx.x * blockDim.x + threadIdx.x;
    if (i < 256 * 96) {
        int r = i / 96, c = i % 96;
        g_Woa[i] = (c < 64) ? Woff[r * 64 + c] : Wattn[r * 32 + (c - 64)];
    }
    if (i < 96) g_boa[i] = (i < 64) ? boff[i] : battn[i - 64];
}

// ---------------- common helpers ----------------
__device__ __forceinline__ void cp16(float* dst_s, const float* src_g, int sz) {
    unsigned int d = (unsigned int)__cvta_generic_to_shared(dst_s);
    asm volatile("cp.async.ca.shared.global [%0], [%1], 16, %2;\n"
                 :: "r"(d), "l"(src_g), "r"(sz));
}

__device__ __forceinline__ void mma_tf32(float* d, const float* a, const float* b) {
    const unsigned int* A = reinterpret_cast<const unsigned int*>(a);
    const unsigned int* Bv = reinterpret_cast<const unsigned int*>(b);
    asm volatile("mma.sync.aligned.m16n8k8.row.col.f32.tf32.tf32.f32 "
                 "{%0,%1,%2,%3}, {%4,%5,%6,%7}, {%8,%9}, {%0,%1,%2,%3};\n"
                 : "+f"(d[0]), "+f"(d[1]), "+f"(d[2]), "+f"(d[3])
                 : "r"(A[0]), "r"(A[1]), "r"(A[2]), "r"(A[3]), "r"(Bv[0]), "r"(Bv[1]));
}

// ================= narrow tf32 GEMM (for N=96 off|attn) =================
// Block 128x128x32, 256 threads (8 warps 2x4), warp tile 64x32.
#define TBM 128
#define TBN 128
#define TBK 32
#define A_LD 36
#define B_LD 136
#define ASZ (TBM * A_LD)
#define BSZ (TBK * B_LD)
#define STAGE_SZ (ASZ + BSZ)
#define GEMM_SMEM_BYTES (2 * STAGE_SZ * 4)

__device__ __forceinline__ void load_tiles(float* As, float* Bs,
                                           const float* __restrict__ A,
                                           const float* __restrict__ B,
                                           int N, int K, int row0, int k0, int tid) {
#pragma unroll
    for (int it = 0; it < 4; it++) {
        int idx = it * 256 + tid;
        int r = idx >> 3;
        int kq = (idx & 7) << 2;
        cp16(As + r * A_LD + kq, A + (size_t)(row0 + r) * K + k0 + kq, 16);
    }
#pragma unroll
    for (int it = 0; it < 4; it++) {
        int idx = it * 256 + tid;
        int r = idx >> 5;
        int nq = (idx & 31) << 2;
        int sz = (nq < N) ? 16 : 0;
        cp16(Bs + r * B_LD + nq, B + (size_t)(k0 + r) * N + (nq < N ? nq : 0), sz);
    }
    asm volatile("cp.async.commit_group;\n");
}

__global__ __launch_bounds__(256)
void gemm_tf32(const float* __restrict__ A, const float* __restrict__ Bm,
               const float* __restrict__ bias, float* __restrict__ C,
               int M, int N, int K) {
    extern __shared__ float sm[];
    int tid  = threadIdx.x;
    int lane = tid & 31;
    int wid  = tid >> 5;
    int g    = lane >> 2;
    int tig  = lane & 3;
    int wm   = wid >> 2;
    int wn   = wid & 3;
    int row0 = blockIdx.y * TBM;

    float acc[4][4][4];
#pragma unroll
    for (int mi = 0; mi < 4; mi++)
#pragma unroll
        for (int ni = 0; ni < 4; ni++)
#pragma unroll
            for (int e = 0; e < 4; e++) acc[mi][ni][e] = 0.f;

    int nk = K / TBK;
    load_tiles(sm, sm + ASZ, A, Bm, N, K, row0, 0, tid);

    for (int kt = 0; kt < nk; kt++) {
        asm volatile("cp.async.wait_group 0;\n");
        __syncthreads();
        if (kt + 1 < nk) {
            int st = (kt + 1) & 1;
            load_tiles(sm + st * STAGE_SZ, sm + st * STAGE_SZ + ASZ,
                       A, Bm, N, K, row0, (kt + 1) * TBK, tid);
        }
        const float* As = sm + (kt & 1) * STAGE_SZ;
        const float* Bs = As + ASZ;

#pragma unroll
        for (int ks = 0; ks < 4; ks++) {
            float af[4][4];
#pragma unroll
            for (int mi = 0; mi < 4; mi++) {
                const float* ap = As + (wm * 64 + mi * 16 + g) * A_LD + ks * 8 + tig;
                af[mi][0] = ap[0];
                af[mi][1] = ap[8 * A_LD];
                af[mi][2] = ap[4];
                af[mi][3] = ap[8 * A_LD + 4];
            }
            float bf[4][2];
#pragma unroll
            for (int ni = 0; ni < 4; ni++) {
                const float* bp = Bs + (ks * 8 + tig) * B_LD + wn * 32 + ni * 8 + g;
                bf[ni][0] = bp[0];
                bf[ni][1] = bp[4 * B_LD];
            }
#pragma unroll
            for (int mi = 0; mi < 4; mi++)
#pragma unroll
                for (int ni = 0; ni < 4; ni++)
                    mma_tf32(acc[mi][ni], af[mi], bf[ni]);
        }
        __syncthreads();
    }

    float bc[4][2];
#pragma unroll
    for (int ni = 0; ni < 4; ni++) {
        int c = wn * 32 + ni * 8 + 2 * tig;
        bc[ni][0] = (c < N) ? bias[c] : 0.f;
        bc[ni][1] = (c < N) ? bias[c + 1] : 0.f;
    }
#pragma unroll
    for (int mi = 0; mi < 4; mi++) {
        int r = row0 + wm * 64 + mi * 16 + g;
#pragma unroll
        for (int ni = 0; ni < 4; ni++) {
            int c = wn * 32 + ni * 8 + 2 * tig;
            if (c < N) {
                float2 o0 = make_float2(acc[mi][ni][0] + bc[ni][0], acc[mi][ni][1] + bc[ni][1]);
                float2 o1 = make_float2(acc[mi][ni][2] + bc[ni][0], acc[mi][ni][3] + bc[ni][1]);
                *(float2*)(C + (size_t)r * N + c)       = o0;
                *(float2*)(C + (size_t)(r + 8) * N + c) = o1;
            }
        }
    }
}

// ================= full-row tf32 GEMM: 128x256 block, optional fused LN =================
// 512 threads, 16 warps (2x8), warp tile 64x32. N fixed to 256.
#define QBM 128
#define QBK 32
#define QA_LD 36
#define QB_LD 264
#define QASZ (QBM * QA_LD)          // 4608
#define QBSZ (QBK * QB_LD)          // 8448
#define QSTG (QASZ + QBSZ)          // 13056 floats
#define Q_SMEM_BYTES (2 * QSTG * 4) // 104448 B

__device__ __forceinline__ void q_load(float* As, float* Bs,
                                       const float* __restrict__ A,
                                       const float* __restrict__ B,
                                       int row0, int k0, int tid) {
#pragma unroll
    for (int it = 0; it < 2; it++) {          // A: 128 x 32 = 1024 quads
        int idx = it * 512 + tid;
        int r = idx >> 3;
        int kq = (idx & 7) << 2;
        cp16(As + r * QA_LD + kq, A + (size_t)(row0 + r) * 256 + k0 + kq, 16);
    }
#pragma unroll
    for (int it = 0; it < 4; it++) {          // B: 32 x 256 = 2048 quads
        int idx = it * 512 + tid;
        int r = idx >> 6;
        int nq = (idx & 63) << 2;
        cp16(Bs + r * QB_LD + nq, B + (size_t)(k0 + r) * 256 + nq, 16);
    }
    asm volatile("cp.async.commit_group;\n");
}

template<bool FUSE_LN>
__global__ __launch_bounds__(512, 1)
void gemm256(const float* __restrict__ A, const float* __restrict__ Bm,
             const float* __restrict__ bias, float* __restrict__ C,
             const float* __restrict__ resid,
             const float* __restrict__ lng, const float* __restrict__ lnb) {
    extern __shared__ float sm[];
    int tid  = threadIdx.x;
    int lane = tid & 31;
    int wid  = tid >> 5;          // 0..15
    int g    = lane >> 2;         // 0..7
    int tig  = lane & 3;          // 0..3
    int wm   = wid >> 3;          // 0..1
    int wn   = wid & 7;           // 0..7
    int row0 = blockIdx.x * QBM;

    float acc[4][4][4];
#pragma unroll
    for (int mi = 0; mi < 4; mi++)
#pragma unroll
        for (int ni = 0; ni < 4; ni++)
#pragma unroll
            for (int e = 0; e < 4; e++) acc[mi][ni][e] = 0.f;

    const int nk = 8;             // K = 256
    q_load(sm, sm + QASZ, A, Bm, row0, 0, tid);

    for (int kt = 0; kt < nk; kt++) {
        asm volatile("cp.async.wait_group 0;\n");
        __syncthreads();
        if (kt + 1 < nk) {
            int st = (kt + 1) & 1;
            q_load(sm + st * QSTG, sm + st * QSTG + QASZ, A, Bm, row0, (kt + 1) * QBK, tid);
        }
        const float* As = sm + (kt & 1) * QSTG;
        const float* Bs = As + QASZ;

#pragma unroll
        for (int ks = 0; ks < 4; ks++) {
            float af[4][4];
#pragma unroll
            for (int mi = 0; mi < 4; mi++) {
                const float* ap = As + (wm * 64 + mi * 16 + g) * QA_LD + ks * 8 + tig;
                af[mi][0] = ap[0];
                af[mi][1] = ap[8 * QA_LD];
                af[mi][2] = ap[4];
                af[mi][3] = ap[8 * QA_LD + 4];
            }
            float bf[4][2];
#pragma unroll
            for (int ni = 0; ni < 4; ni++) {
                const float* bp = Bs + (ks * 8 + tig) * QB_LD + wn * 32 + ni * 8 + g;
                bf[ni][0] = bp[0];
                bf[ni][1] = bp[4 * QB_LD];
            }
#pragma unroll
            for (int mi = 0; mi < 4; mi++)
#pragma unroll
                for (int ni = 0; ni < 4; ni++)
                    mma_tf32(acc[mi][ni], af[mi], bf[ni]);
        }
        __syncthreads();
    }

    if (!FUSE_LN) {
        // plain: bias + store
#pragma unroll
        for (int mi = 0; mi < 4; mi++) {
            int r = row0 + wm * 64 + mi * 16 + g;
#pragma unroll
            for (int ni = 0; ni < 4; ni++) {
                int c = wn * 32 + ni * 8 + 2 * tig;
                float b0 = bias[c], b1 = bias[c + 1];
                float2 o0 = make_float2(acc[mi][ni][0] + b0, acc[mi][ni][1] + b1);
                float2 o1 = make_float2(acc[mi][ni][2] + b0, acc[mi][ni][3] + b1);
                *(float2*)(C + (size_t)r * 256 + c)       = o0;
                *(float2*)(C + (size_t)(r + 8) * 256 + c) = o1;
            }
        }
        return;
    }

    // ---- fused: x = acc + bias + resid; out = LN(x) ----
    float sum0[4], sq0[4], sum1[4], sq1[4];
#pragma unroll
    for (int mi = 0; mi < 4; mi++) { sum0[mi] = sq0[mi] = sum1[mi] = sq1[mi] = 0.f; }

#pragma unroll
    for (int mi = 0; mi < 4; mi++) {
        int r = row0 + wm * 64 + mi * 16 + g;
#pragma unroll
        for (int ni = 0; ni < 4; ni++) {
            int c = wn * 32 + ni * 8 + 2 * tig;
            float b0 = bias[c], b1 = bias[c + 1];
            float2 t0 = *(const float2*)(resid + (size_t)r * 256 + c);
            float2 t1 = *(const float2*)(resid + (size_t)(r + 8) * 256 + c);
            acc[mi][ni][0] += b0 + t0.x;
            acc[mi][ni][1] += b1 + t0.y;
            acc[mi][ni][2] += b0 + t1.x;
            acc[mi][ni][3] += b1 + t1.y;
            sum0[mi] += acc[mi][ni][0] + acc[mi][ni][1];
            sq0[mi]  += acc[mi][ni][0] * acc[mi][ni][0] + acc[mi][ni][1] * acc[mi][ni][1];
            sum1[mi] += acc[mi][ni][2] + acc[mi][ni][3];
            sq1[mi]  += acc[mi][ni][2] * acc[mi][ni][2] + acc[mi][ni][3] * acc[mi][ni][3];
        }
        // reduce over the 4 tig lanes (consecutive lanes sharing g)
#pragma unroll
        for (int o = 1; o <= 2; o <<= 1) {
            sum0[mi] += __shfl_xor_sync(0xffffffffu, sum0[mi], o);
            sq0[mi]  += __shfl_xor_sync(0xffffffffu, sq0[mi],  o);
            sum1[mi] += __shfl_xor_sync(0xffffffffu, sum1[mi], o);
            sq1[mi]  += __shfl_xor_sync(0xffffffffu, sq1[mi],  o);
        }
    }

    // smem scratch (pipeline buffers are free after the loop's trailing barrier):
    // s_sum[128][8] at sm[0..1024), s_sq at sm[1024..2048), m/rs pairs at sm[2048..2304)
    if (tig == 0) {
#pragma unroll
        for (int mi = 0; mi < 4; mi++) {
            int rl0 = wm * 64 + mi * 16 + g;
            int rl1 = rl0 + 8;
            sm[rl0 * 8 + wn]        = sum0[mi];
            sm[1024 + rl0 * 8 + wn] = sq0[mi];
            sm[rl1 * 8 + wn]        = sum1[mi];
            sm[1024 + rl1 * 8 + wn] = sq1[mi];
        }
    }
    __syncthreads();

    if (tid < 128) {
        float s = 0.f, ss = 0.f;
#pragma unroll
        for (int j = 0; j < 8; j++) {
            s  += sm[tid * 8 + j];
            ss += sm[1024 + tid * 8 + j];
        }
        float m   = s * (1.f / 256.f);
        float var = ss * (1.f / 256.f) - m * m;
        float rs  = rsqrtf(var + 1e-5f);
        *(float2*)(sm + 2048 + tid * 2) = make_float2(m, rs);
    }
    __syncthreads();

#pragma unroll
    for (int mi = 0; mi < 4; mi++) {
        int rl0 = wm * 64 + mi * 16 + g;
        int rl1 = rl0 + 8;
        float2 mr0 = *(float2*)(sm + 2048 + rl0 * 2);
        float2 mr1 = *(float2*)(sm + 2048 + rl1 * 2);
        int r = row0 + rl0;
#pragma unroll
        for (int ni = 0; ni < 4; ni++) {
            int c = wn * 32 + ni * 8 + 2 * tig;
            float gx = lng[c], gy = lng[c + 1];
            float bx = lnb[c], by = lnb[c + 1];
            float2 o0 = make_float2((acc[mi][ni][0] - mr0.x) * mr0.y * gx + bx,
                                    (acc[mi][ni][1] - mr0.x) * mr0.y * gy + by);
            float2 o1 = make_float2((acc[mi][ni][2] - mr1.x) * mr1.y * gx + bx,
                                    (acc[mi][ni][3] - mr1.x) * mr1.y * gy + by);
            *(float2*)(C + (size_t)r * 256 + c)       = o0;
            *(float2*)(C + (size_t)(r + 8) * 256 + c) = o1;
        }
    }
}

// ---------------- deformable bilinear sampling (float4 channels) ----------------
__global__ __launch_bounds__(256)
void sample_kernel(const float* __restrict__ refp) {
    int t  = threadIdx.x;
    int q  = blockIdx.x * 4 + (t >> 6);
    int h  = (t >> 3) & 7;
    int ci = (t & 7) << 2;
    int b  = q >> 13;

    const float* oa = g_offattn + (size_t)q * 96;
    float rx = refp[q * 2 + 0];
    float ry = refp[q * 2 + 1];

    float a0 = oa[64 + h * 4 + 0];
    float a1 = oa[64 + h * 4 + 1];
    float a2 = oa[64 + h * 4 + 2];
    float a3 = oa[64 + h * 4 + 3];
    float mx = fmaxf(fmaxf(a0, a1), fmaxf(a2, a3));
    float e0 = expf(a0 - mx), e1 = expf(a1 - mx), e2 = expf(a2 - mx), e3 = expf(a3 - mx);
    float inv = 1.f / (e0 + e1 + e2 + e3);
    float aw[4] = {e0 * inv, e1 * inv, e2 * inv, e3 * inv};

    const float* vb = g_value + (size_t)b * S_ * D_ + h * DH_ + ci;
    float4 acc = make_float4(0.f, 0.f, 0.f, 0.f);

#pragma unroll
    for (int p = 0; p < NP_; p++) {
        float ox = oa[h * 8 + p * 2 + 0];
        float oy = oa[h * 8 + p * 2 + 1];
        float xf = rx * (float)WW_ + ox - 0.5f;
        float yf = ry * (float)HH_ + oy - 0.5f;
        float x0f = floorf(xf), y0f = floorf(yf);
        int x0 = (int)x0f, y0 = (int)y0f;
        float wx1 = xf - x0f, wy1 = yf - y0f;
        float wx0 = 1.f - wx1, wy0 = 1.f - wy1;
        float w00 = wy0 * wx0 * aw[p];
        float w01 = wy0 * wx1 * aw[p];
        float w10 = wy1 * wx0 * aw[p];
        float w11 = wy1 * wx1 * aw[p];
        int x1 = x0 + 1, y1 = y0 + 1;
        bool xin0 = (unsigned)x0 < (unsigned)WW_;
        bool xin1 = (unsigned)x1 < (unsigned)WW_;
        if ((unsigned)y0 < (unsigned)HH_) {
            if (xin0) {
                float4 v = *(const float4*)(vb + (size_t)(y0 * WW_ + x0) * D_);
                acc.x += w00 * v.x; acc.y += w00 * v.y; acc.z += w00 * v.z; acc.w += w00 * v.w;
            }
            if (xin1) {
                float4 v = *(const float4*)(vb + (size_t)(y0 * WW_ + x1) * D_);
                acc.x += w01 * v.x; acc.y += w01 * v.y; acc.z += w01 * v.z; acc.w += w01 * v.w;
            }
        }
        if ((unsigned)y1 < (unsigned)HH_) {
            if (xin0) {
                float4 v = *(const float4*)(vb + (size_t)(y1 * WW_ + x0) * D_);
                acc.x += w10 * v.x; acc.y += w10 * v.y; acc.z += w10 * v.z; acc.w += w10 * v.w;
            }
            if (xin1) {
                float4 v = *(const float4*)(vb + (size_t)(y1 * WW_ + x1) * D_);
                acc.x += w11 * v.x; acc.y += w11 * v.y; acc.z += w11 * v.z; acc.w += w11 * v.w;
            }
        }
    }
    *(float4*)(g_sampled + (size_t)q * D_ + h * DH_ + ci) = acc;
}

// ---------------- LN(2*src): reads src ONCE ----------------
__global__ __launch_bounds__(256)
void ln2_kernel(const float* __restrict__ A,
                const float* __restrict__ g, const float* __restrict__ bb,
                float* __restrict__ out, int rows) {
    int w = (blockIdx.x * blockDim.x + threadIdx.x) >> 5;
    if (w >= rows) return;
    int lane = threadIdx.x & 31;

    const float4* A4 = (const float4*)A + (size_t)w * 64;
    float4 xa = A4[lane];
    float4 ya = A4[lane + 32];
    float4 x = make_float4(2.f * xa.x, 2.f * xa.y, 2.f * xa.z, 2.f * xa.w);
    float4 y = make_float4(2.f * ya.x, 2.f * ya.y, 2.f * ya.z, 2.f * ya.w);

    float s  = x.x + x.y + x.z + x.w + y.x + y.y + y.z + y.w;
    float ss = x.x * x.x + x.y * x.y + x.z * x.z + x.w * x.w
             + y.x * y.x + y.y * y.y + y.z * y.z + y.w * y.w;
#pragma unroll
    for (int o = 16; o > 0; o >>= 1) {
        s  += __shfl_xor_sync(0xffffffffu, s, o);
        ss += __shfl_xor_sync(0xffffffffu, ss, o);
    }
    float m   = s * (1.f / 256.f);
    float var = ss * (1.f / 256.f) - m * m;
    float rs  = rsqrtf(var + 1e-5f);

    const float4* g4 = (const float4*)g;
    const float4* b4 = (const float4*)bb;
    float4 g0 = g4[lane], g1 = g4[lane + 32];
    float4 c0 = b4[lane], c1 = b4[lane + 32];

    float4 o0, o1;
    o0.x = (x.x - m) * rs * g0.x + c0.x;
    o0.y = (x.y - m) * rs * g0.y + c0.y;
    o0.z = (x.z - m) * rs * g0.z + c0.z;
    o0.w = (x.w - m) * rs * g0.w + c0.w;
    o1.x = (y.x - m) * rs * g1.x + c1.x;
    o1.y = (y.y - m) * rs * g1.y + c1.y;
    o1.z = (y.z - m) * rs * g1.z + c1.z;
    o1.w = (y.w - m) * rs * g1.w + c1.w;

    float4* O4 = (float4*)out + (size_t)w * 64;
    O4[lane]      = o0;
    O4[lane + 32] = o1;
}

// ---------------- launch ----------------
extern "C" void kernel_launch(void* const* d_in, const int* in_sizes, int n_in,
                              void* d_out, int out_size) {
    const float* tgt    = (const float*)d_in[0];
    const float* src    = (const float*)d_in[1];
    const float* refp   = (const float*)d_in[2];
    const float* Wv     = (const float*)d_in[3];
    const float* bv     = (const float*)d_in[4];
    const float* Woff   = (const float*)d_in[5];
    const float* boff   = (const float*)d_in[6];
    const float* Wattn  = (const float*)d_in[7];
    const float* battn  = (const float*)d_in[8];
    const float* Wout   = (const float*)d_in[9];
    const float* bout   = (const float*)d_in[10];
    const float* ln1g   = (const float*)d_in[11];
    const float* ln1b   = (const float*)d_in[12];
    const float* ln2g   = (const float*)d_in[13];
    const float* ln2b   = (const float*)d_in[14];

    float* out = (float*)d_out;

    float *p_value, *p_offattn, *p_sampled, *p_Woa, *p_boa;
    cudaGetSymbolAddress((void**)&p_value,   g_value);
    cudaGetSymbolAddress((void**)&p_offattn, g_offattn);
    cudaGetSymbolAddress((void**)&p_sampled, g_sampled);
    cudaGetSymbolAddress((void**)&p_Woa,     g_Woa);
    cudaGetSymbolAddress((void**)&p_boa,     g_boa);

    cudaFuncSetAttribute(gemm_tf32, cudaFuncAttributeMaxDynamicSharedMemorySize,
                         GEMM_SMEM_BYTES);
    cudaFuncSetAttribute(gemm256<false>, cudaFuncAttributeMaxDynamicSharedMemorySize,
                         Q_SMEM_BYTES);
    cudaFuncSetAttribute(gemm256<true>, cudaFuncAttributeMaxDynamicSharedMemorySize,
                         Q_SMEM_BYTES);

    // 0) pack off/attn weights
    pack_w_kernel<<<(256 * 96 + 255) / 256, 256>>>(Woff, boff, Wattn, battn);

    // 1) value = src @ W_value + b_value   [65536,256]  (full-row blocks)
    gemm256<false><<<NS_ / QBM, 512, Q_SMEM_BYTES>>>(src, Wv, bv, p_value,
                                                     nullptr, nullptr, nullptr);

    // 2) off|attn = tgt @ [W_off|W_attn] + bias   [32768,96]
    {
        dim3 grid(1, NQ_ / TBM);
        gemm_tf32<<<grid, 256, GEMM_SMEM_BYTES>>>(tgt, p_Woa, p_boa, p_offattn, NQ_, 96, D_);
    }

    // 3) deformable sampling -> g_sampled [32768,256]
    sample_kernel<<<NQ_ / 4, 256>>>(refp);

    // 4+5) query = LN(tgt + sampled @ W_out + b_out) fused -> out[0 : NQ*D]
    gemm256<true><<<NQ_ / QBM, 512, Q_SMEM_BYTES>>>(p_sampled, Wout, bout, out,
                                                    tgt, ln1g, ln1b);

    // 6) src_out = LN(2*src) -> out[NQ*D : ...]
    ln2_kernel<<<(NS_ * 32 + 255) / 256, 256>>>(src, ln2g, ln2b, out + (size_t)NQ_ * D_, NS_);
}

// round 8
// speedup vs baseline: 1.5279x; 1.5279x over previous
#include <cuda_runtime.h>
#include <cuda_bf16.h>
#include <cstdint>
#include <math.h>

// Problem constants
#define B_   4
#define LQ_  8192
#define S_   16384
#define D_   256
#define NH_  8
#define NP_  4
#define DH_  32
#define HH_  128
#define WW_  128
#define NQ_  (B_ * LQ_)   // 32768
#define NS_  (B_ * S_)    // 65536

// ---------------- scratch (static __device__ — no allocations) ----------------
__device__ float g_value[(size_t)NS_ * D_];       // 64 MB
__device__ float g_offattn[(size_t)NQ_ * 96];     // 12 MB
__device__ float g_sampled[(size_t)NQ_ * D_];     // 32 MB
__device__ float g_attnout[(size_t)NQ_ * D_];     // 32 MB
__device__ float g_Woa[256 * 96];
__device__ float g_boa[96];

// ---------------- pack W_off | W_attn into one [256,96] weight ----------------
__global__ void pack_w_kernel(const float* __restrict__ Woff, const float* __restrict__ boff,
                              const float* __restrict__ Wattn, const float* __restrict__ battn) {
    int i = blockIdx.x * blockDim.x + threadIdx.x;
    if (i < 256 * 96) {
        int r = i / 96, c = i % 96;
        g_Woa[i] = (c < 64) ? Woff[r * 64 + c] : Wattn[r * 32 + (c - 64)];
    }
    if (i < 96) g_boa[i] = (i < 64) ? boff[i] : battn[i - 64];
}

// ================= tf32 tensor-core GEMM (R6-proven) =================
// C[M,N] = A[M,K] @ B[K,N] + bias, fp32 in/out, tf32 mma.m16n8k8 accum fp32.
// Block 128x128x32, 256 threads (8 warps, 2x4), warp tile 64x32.
#define TBM 128
#define TBN 128
#define TBK 32
#define A_LD 36     // 128 rows x 36 floats (pad 4)
#define B_LD 136    // 32 k-rows x 136 floats (pad 8)
#define ASZ (TBM * A_LD)         // 4608 floats
#define BSZ (TBK * B_LD)         // 4352 floats
#define STAGE_SZ (ASZ + BSZ)     // 8960 floats
#define GEMM_SMEM_BYTES (2 * STAGE_SZ * 4)   // 71680 B

__device__ __forceinline__ void cp16(float* dst_s, const float* src_g, int sz) {
    unsigned int d = (unsigned int)__cvta_generic_to_shared(dst_s);
    asm volatile("cp.async.ca.shared.global [%0], [%1], 16, %2;\n"
                 :: "r"(d), "l"(src_g), "r"(sz));
}

__device__ __forceinline__ void load_tiles(float* As, float* Bs,
                                           const float* __restrict__ A,
                                           const float* __restrict__ B,
                                           int N, int K, int row0, int col0, int k0, int tid) {
#pragma unroll
    for (int it = 0; it < 4; it++) {           // A: 128 rows x 8 quads
        int idx = it * 256 + tid;
        int r = idx >> 3;
        int kq = (idx & 7) << 2;
        cp16(As + r * A_LD + kq, A + (size_t)(row0 + r) * K + k0 + kq, 16);
    }
#pragma unroll
    for (int it = 0; it < 4; it++) {           // B: 32 k-rows x 32 quads
        int idx = it * 256 + tid;
        int r = idx >> 5;
        int nq = (idx & 31) << 2;
        int sz = (col0 + nq < N) ? 16 : 0;
        cp16(Bs + r * B_LD + nq, B + (size_t)(k0 + r) * N + (col0 + nq < N ? col0 + nq : 0), sz);
    }
    asm volatile("cp.async.commit_group;\n");
}

__device__ __forceinline__ void mma_tf32(float* d, const float* a, const float* b) {
    const unsigned int* A = reinterpret_cast<const unsigned int*>(a);
    const unsigned int* Bv = reinterpret_cast<const unsigned int*>(b);
    asm volatile("mma.sync.aligned.m16n8k8.row.col.f32.tf32.tf32.f32 "
                 "{%0,%1,%2,%3}, {%4,%5,%6,%7}, {%8,%9}, {%0,%1,%2,%3};\n"
                 : "+f"(d[0]), "+f"(d[1]), "+f"(d[2]), "+f"(d[3])
                 : "r"(A[0]), "r"(A[1]), "r"(A[2]), "r"(A[3]), "r"(Bv[0]), "r"(Bv[1]));
}

__global__ __launch_bounds__(256)
void gemm_tf32(const float* __restrict__ A, const float* __restrict__ Bm,
               const float* __restrict__ bias, float* __restrict__ C,
               int M, int N, int K) {
    extern __shared__ float sm[];
    int tid  = threadIdx.x;
    int lane = tid & 31;
    int wid  = tid >> 5;
    int g    = lane >> 2;       // 0..7
    int tig  = lane & 3;        // 0..3
    int wm   = wid >> 2;        // 0..1
    int wn   = wid & 3;         // 0..3
    int row0 = blockIdx.y * TBM;
    int col0 = blockIdx.x * TBN;

    float acc[4][4][4];
#pragma unroll
    for (int mi = 0; mi < 4; mi++)
#pragma unroll
        for (int ni = 0; ni < 4; ni++)
#pragma unroll
            for (int e = 0; e < 4; e++) acc[mi][ni][e] = 0.f;

    int nk = K / TBK;
    load_tiles(sm, sm + ASZ, A, Bm, N, K, row0, col0, 0, tid);

    for (int kt = 0; kt < nk; kt++) {
        asm volatile("cp.async.wait_group 0;\n");
        __syncthreads();
        if (kt + 1 < nk) {
            int st = (kt + 1) & 1;
            load_tiles(sm + st * STAGE_SZ, sm + st * STAGE_SZ + ASZ,
                       A, Bm, N, K, row0, col0, (kt + 1) * TBK, tid);
        }
        const float* As = sm + (kt & 1) * STAGE_SZ;
        const float* Bs = As + ASZ;

#pragma unroll
        for (int ks = 0; ks < 4; ks++) {
            float af[4][4];
#pragma unroll
            for (int mi = 0; mi < 4; mi++) {
                const float* ap = As + (wm * 64 + mi * 16 + g) * A_LD + ks * 8 + tig;
                af[mi][0] = ap[0];
                af[mi][1] = ap[8 * A_LD];
                af[mi][2] = ap[4];
                af[mi][3] = ap[8 * A_LD + 4];
            }
            float bf[4][2];
#pragma unroll
            for (int ni = 0; ni < 4; ni++) {
                const float* bp = Bs + (ks * 8 + tig) * B_LD + wn * 32 + ni * 8 + g;
                bf[ni][0] = bp[0];
                bf[ni][1] = bp[4 * B_LD];
            }
#pragma unroll
            for (int mi = 0; mi < 4; mi++)
#pragma unroll
                for (int ni = 0; ni < 4; ni++)
                    mma_tf32(acc[mi][ni], af[mi], bf[ni]);
        }
        __syncthreads();
    }

    // epilogue: bias + store
    float bc[4][2];
#pragma unroll
    for (int ni = 0; ni < 4; ni++) {
        int c = col0 + wn * 32 + ni * 8 + 2 * tig;
        bc[ni][0] = (c < N) ? bias[c] : 0.f;
        bc[ni][1] = (c < N) ? bias[c + 1] : 0.f;
    }
#pragma unroll
    for (int mi = 0; mi < 4; mi++) {
        int r = row0 + wm * 64 + mi * 16 + g;
#pragma unroll
        for (int ni = 0; ni < 4; ni++) {
            int c = col0 + wn * 32 + ni * 8 + 2 * tig;
            if (c < N) {
                float2 o0 = make_float2(acc[mi][ni][0] + bc[ni][0], acc[mi][ni][1] + bc[ni][1]);
                float2 o1 = make_float2(acc[mi][ni][2] + bc[ni][0], acc[mi][ni][3] + bc[ni][1]);
                *(float2*)(C + (size_t)r * N + c)       = o0;
                *(float2*)(C + (size_t)(r + 8) * N + c) = o1;
            }
        }
    }
}

// ---------------- deformable bilinear sampling (float4 channels) ----------------
// 256 threads = 4 queries; per query: 8 heads x 8 threads, each thread 4 channels.
__global__ __launch_bounds__(256)
void sample_kernel(const float* __restrict__ refp) {
    int t  = threadIdx.x;
    int q  = blockIdx.x * 4 + (t >> 6);
    int h  = (t >> 3) & 7;
    int ci = (t & 7) << 2;
    int b  = q >> 13;            // q / LQ_

    const float* oa = g_offattn + (size_t)q * 96;
    float rx = refp[q * 2 + 0];
    float ry = refp[q * 2 + 1];

    float a0 = oa[64 + h * 4 + 0];
    float a1 = oa[64 + h * 4 + 1];
    float a2 = oa[64 + h * 4 + 2];
    float a3 = oa[64 + h * 4 + 3];
    float mx = fmaxf(fmaxf(a0, a1), fmaxf(a2, a3));
    float e0 = expf(a0 - mx), e1 = expf(a1 - mx), e2 = expf(a2 - mx), e3 = expf(a3 - mx);
    float inv = 1.f / (e0 + e1 + e2 + e3);
    float aw[4] = {e0 * inv, e1 * inv, e2 * inv, e3 * inv};

    const float* vb = g_value + (size_t)b * S_ * D_ + h * DH_ + ci;
    float4 acc = make_float4(0.f, 0.f, 0.f, 0.f);

#pragma unroll
    for (int p = 0; p < NP_; p++) {
        float ox = oa[h * 8 + p * 2 + 0];
        float oy = oa[h * 8 + p * 2 + 1];
        float xf = rx * (float)WW_ + ox - 0.5f;
        float yf = ry * (float)HH_ + oy - 0.5f;
        float x0f = floorf(xf), y0f = floorf(yf);
        int x0 = (int)x0f, y0 = (int)y0f;
        float wx1 = xf - x0f, wy1 = yf - y0f;
        float wx0 = 1.f - wx1, wy0 = 1.f - wy1;
        float w00 = wy0 * wx0 * aw[p];
        float w01 = wy0 * wx1 * aw[p];
        float w10 = wy1 * wx0 * aw[p];
        float w11 = wy1 * wx1 * aw[p];
        int x1 = x0 + 1, y1 = y0 + 1;
        bool xin0 = (unsigned)x0 < (unsigned)WW_;
        bool xin1 = (unsigned)x1 < (unsigned)WW_;
        if ((unsigned)y0 < (unsigned)HH_) {
            if (xin0) {
                float4 v = *(const float4*)(vb + (size_t)(y0 * WW_ + x0) * D_);
                acc.x += w00 * v.x; acc.y += w00 * v.y; acc.z += w00 * v.z; acc.w += w00 * v.w;
            }
            if (xin1) {
                float4 v = *(const float4*)(vb + (size_t)(y0 * WW_ + x1) * D_);
                acc.x += w01 * v.x; acc.y += w01 * v.y; acc.z += w01 * v.z; acc.w += w01 * v.w;
            }
        }
        if ((unsigned)y1 < (unsigned)HH_) {
            if (xin0) {
                float4 v = *(const float4*)(vb + (size_t)(y1 * WW_ + x0) * D_);
                acc.x += w10 * v.x; acc.y += w10 * v.y; acc.z += w10 * v.z; acc.w += w10 * v.w;
            }
            if (xin1) {
                float4 v = *(const float4*)(vb + (size_t)(y1 * WW_ + x1) * D_);
                acc.x += w11 * v.x; acc.y += w11 * v.y; acc.z += w11 * v.z; acc.w += w11 * v.w;
            }
        }
    }
    *(float4*)(g_sampled + (size_t)q * D_ + h * DH_ + ci) = acc;
}

// ---------------- fused residual + LayerNorm over 256-wide rows ----------------
__global__ __launch_bounds__(256)
void ln_fused(const float* __restrict__ A, const float* __restrict__ Bp,
              const float* __restrict__ g, const float* __restrict__ bb,
              float* __restrict__ out, int rows) {
    int w = (blockIdx.x * blockDim.x + threadIdx.x) >> 5;
    if (w >= rows) return;
    int lane = threadIdx.x & 31;

    const float4* A4 = (const float4*)A + (size_t)w * 64;
    const float4* B4 = (const float4*)Bp + (size_t)w * 64;

    float4 xa = A4[lane];
    float4 xb = B4[lane];
    float4 ya = A4[lane + 32];
    float4 yb = B4[lane + 32];
    float4 x = make_float4(xa.x + xb.x, xa.y + xb.y, xa.z + xb.z, xa.w + xb.w);
    float4 y = make_float4(ya.x + yb.x, ya.y + yb.y, ya.z + yb.z, ya.w + yb.w);

    float s  = x.x + x.y + x.z + x.w + y.x + y.y + y.z + y.w;
    float ss = x.x * x.x + x.y * x.y + x.z * x.z + x.w * x.w
             + y.x * y.x + y.y * y.y + y.z * y.z + y.w * y.w;
#pragma unroll
    for (int o = 16; o > 0; o >>= 1) {
        s  += __shfl_xor_sync(0xffffffffu, s, o);
        ss += __shfl_xor_sync(0xffffffffu, ss, o);
    }
    float m   = s * (1.f / 256.f);
    float var = ss * (1.f / 256.f) - m * m;
    float rs  = rsqrtf(var + 1e-5f);

    const float4* g4 = (const float4*)g;
    const float4* b4 = (const float4*)bb;
    float4 g0 = g4[lane], g1 = g4[lane + 32];
    float4 c0 = b4[lane], c1 = b4[lane + 32];

    float4 o0, o1;
    o0.x = (x.x - m) * rs * g0.x + c0.x;
    o0.y = (x.y - m) * rs * g0.y + c0.y;
    o0.z = (x.z - m) * rs * g0.z + c0.z;
    o0.w = (x.w - m) * rs * g0.w + c0.w;
    o1.x = (y.x - m) * rs * g1.x + c1.x;
    o1.y = (y.y - m) * rs * g1.y + c1.y;
    o1.z = (y.z - m) * rs * g1.z + c1.z;
    o1.w = (y.w - m) * rs * g1.w + c1.w;

    float4* O4 = (float4*)out + (size_t)w * 64;
    O4[lane]      = o0;
    O4[lane + 32] = o1;
}

// ---------------- LN(2*src): reads src ONCE ----------------
__global__ __launch_bounds__(256)
void ln2_kernel(const float* __restrict__ A,
                const float* __restrict__ g, const float* __restrict__ bb,
                float* __restrict__ out, int rows) {
    int w = (blockIdx.x * blockDim.x + threadIdx.x) >> 5;
    if (w >= rows) return;
    int lane = threadIdx.x & 31;

    const float4* A4 = (const float4*)A + (size_t)w * 64;
    float4 xa = A4[lane];
    float4 ya = A4[lane + 32];
    float4 x = make_float4(2.f * xa.x, 2.f * xa.y, 2.f * xa.z, 2.f * xa.w);
    float4 y = make_float4(2.f * ya.x, 2.f * ya.y, 2.f * ya.z, 2.f * ya.w);

    float s  = x.x + x.y + x.z + x.w + y.x + y.y + y.z + y.w;
    float ss = x.x * x.x + x.y * x.y + x.z * x.z + x.w * x.w
             + y.x * y.x + y.y * y.y + y.z * y.z + y.w * y.w;
#pragma unroll
    for (int o = 16; o > 0; o >>= 1) {
        s  += __shfl_xor_sync(0xffffffffu, s, o);
        ss += __shfl_xor_sync(0xffffffffu, ss, o);
    }
    float m   = s * (1.f / 256.f);
    float var = ss * (1.f / 256.f) - m * m;
    float rs  = rsqrtf(var + 1e-5f);

    const float4* g4 = (const float4*)g;
    const float4* b4 = (const float4*)bb;
    float4 g0 = g4[lane], g1 = g4[lane + 32];
    float4 c0 = b4[lane], c1 = b4[lane + 32];

    float4 o0, o1;
    o0.x = (x.x - m) * rs * g0.x + c0.x;
    o0.y = (x.y - m) * rs * g0.y + c0.y;
    o0.z = (x.z - m) * rs * g0.z + c0.z;
    o0.w = (x.w - m) * rs * g0.w + c0.w;
    o1.x = (y.x - m) * rs * g1.x + c1.x;
    o1.y = (y.y - m) * rs * g1.y + c1.y;
    o1.z = (y.z - m) * rs * g1.z + c1.z;
    o1.w = (y.w - m) * rs * g1.w + c1.w;

    float4* O4 = (float4*)out + (size_t)w * 64;
    O4[lane]      = o0;
    O4[lane + 32] = o1;
}

// ---------------- launch ----------------
extern "C" void kernel_launch(void* const* d_in, const int* in_sizes, int n_in,
                              void* d_out, int out_size) {
    const float* tgt    = (const float*)d_in[0];
    const float* src    = (const float*)d_in[1];
    const float* refp   = (const float*)d_in[2];
    const float* Wv     = (const float*)d_in[3];
    const float* bv     = (const float*)d_in[4];
    const float* Woff   = (const float*)d_in[5];
    const float* boff   = (const float*)d_in[6];
    const float* Wattn  = (const float*)d_in[7];
    const float* battn  = (const float*)d_in[8];
    const float* Wout   = (const float*)d_in[9];
    const float* bout   = (const float*)d_in[10];
    const float* ln1g   = (const float*)d_in[11];
    const float* ln1b   = (const float*)d_in[12];
    const float* ln2g   = (const float*)d_in[13];
    const float* ln2b   = (const float*)d_in[14];

    float* out = (float*)d_out;

    float *p_value, *p_offattn, *p_sampled, *p_attnout, *p_Woa, *p_boa;
    cudaGetSymbolAddress((void**)&p_value,   g_value);
    cudaGetSymbolAddress((void**)&p_offattn, g_offattn);
    cudaGetSymbolAddress((void**)&p_sampled, g_sampled);
    cudaGetSymbolAddress((void**)&p_attnout, g_attnout);
    cudaGetSymbolAddress((void**)&p_Woa,     g_Woa);
    cudaGetSymbolAddress((void**)&p_boa,     g_boa);

    cudaFuncSetAttribute(gemm_tf32, cudaFuncAttributeMaxDynamicSharedMemorySize,
                         GEMM_SMEM_BYTES);

    // 0) pack off/attn weights
    pack_w_kernel<<<(256 * 96 + 255) / 256, 256>>>(Woff, boff, Wattn, battn);

    // 1) value = src @ W_value + b_value   [65536,256]
    {
        dim3 grid(D_ / TBN, NS_ / TBM);
        gemm_tf32<<<grid, 256, GEMM_SMEM_BYTES>>>(src, Wv, bv, p_value, NS_, D_, D_);
    }

    // 2) off|attn = tgt @ [W_off|W_attn] + bias   [32768,96]
    {
        dim3 grid(1, NQ_ / TBM);
        gemm_tf32<<<grid, 256, GEMM_SMEM_BYTES>>>(tgt, p_Woa, p_boa, p_offattn, NQ_, 96, D_);
    }

    // 3) deformable sampling -> g_sampled [32768,256]
    sample_kernel<<<NQ_ / 4, 256>>>(refp);

    // 4) attn_out = sampled @ W_out + b_out   [32768,256]
    {
        dim3 grid(D_ / TBN, NQ_ / TBM);
        gemm_tf32<<<grid, 256, GEMM_SMEM_BYTES>>>(p_sampled, Wout, bout, p_attnout, NQ_, D_, D_);
    }

    // 5) query = LN(tgt + attn_out) -> out[0 : NQ*D]
    ln_fused<<<(NQ_ * 32 + 255) / 256, 256>>>(tgt, p_attnout, ln1g, ln1b, out, NQ_);

    // 6) src_out = LN(2*src) -> out[NQ*D : ...]
    ln2_kernel<<<(NS_ * 32 + 255) / 256, 256>>>(src, ln2g, ln2b, out + (size_t)NQ_ * D_, NS_);
}

// round 10
// speedup vs baseline: 1.5765x; 1.0318x over previous
#include <cuda_runtime.h>
#include <cuda_fp16.h>
#include <cstdint>
#include <math.h>

// Problem constants
#define B_   4
#define LQ_  8192
#define S_   16384
#define D_   256
#define NH_  8
#define NP_  4
#define DH_  32
#define HH_  128
#define WW_  128
#define NQ_  (B_ * LQ_)   // 32768
#define NS_  (B_ * S_)    // 65536

// ---------------- scratch (static __device__, 16B-aligned via uint4) ----------------
__device__ uint4 g_srch_raw[(size_t)NS_ * D_ / 8];      // src fp16, 32 MB
__device__ uint4 g_tgth_raw[(size_t)NQ_ * D_ / 8];      // tgt fp16, 16 MB
__device__ uint4 g_value_raw[(size_t)NS_ * D_ / 8];     // value fp16, 32 MB
__device__ uint4 g_sampled_raw[(size_t)NQ_ * D_ / 8];   // sampled fp16, 16 MB
__device__ float g_offattn[(size_t)NQ_ * 96];           // fp32, 12 MB
__device__ float g_attnout[(size_t)NQ_ * D_];           // fp32, 32 MB
__device__ uint4 g_WvT_raw[256 * 256 / 8];              // Wv^T fp16 [N][K]
__device__ uint4 g_WoutT_raw[256 * 256 / 8];            // Wout^T fp16 [N][K]
__device__ uint4 g_WoaT_raw[96 * 256 / 8];              // [Woff|Wattn]^T fp16 [96][K]
__device__ float g_boa[96];

// ---------------- fp32 -> fp16 convert (vectorized) ----------------
__global__ void cvt_f2h(const float* __restrict__ in, __half* __restrict__ outp, int n4) {
    int i = blockIdx.x * blockDim.x + threadIdx.x;
    if (i >= n4) return;
    float4 v = ((const float4*)in)[i];
    __half2 lo = __floats2half2_rn(v.x, v.y);
    __half2 hi = __floats2half2_rn(v.z, v.w);
    ((uint2*)outp)[i] = make_uint2(*(unsigned*)&lo, *(unsigned*)&hi);
}

// ---------------- pack + transpose weights to fp16 [N][K] ----------------
__global__ void pack_wT_kernel(const float* __restrict__ Wv, const float* __restrict__ Wout,
                               const float* __restrict__ Woff, const float* __restrict__ boff,
                               const float* __restrict__ Wattn, const float* __restrict__ battn) {
    int i = blockIdx.x * blockDim.x + threadIdx.x;   // over 256*256
    if (i < 256 * 256) {
        int n = i / 256, k = i % 256;
        ((__half*)g_WvT_raw)[n * 256 + k]   = __float2half_rn(Wv[k * 256 + n]);
        ((__half*)g_WoutT_raw)[n * 256 + k] = __float2half_rn(Wout[k * 256 + n]);
        if (n < 96) {
            float w = (n < 64) ? Woff[k * 64 + n] : Wattn[k * 32 + (n - 64)];
            ((__half*)g_WoaT_raw)[n * 256 + k] = __float2half_rn(w);
        }
    }
    if (i < 96) g_boa[i] = (i < 64) ? boff[i] : battn[i - 64];
}

// ================= fp16 tensor-core GEMM =================
// C[M,N] = A[M,K] @ BT[N,K]^T + bias. A fp16 row-major, BT fp16 [N][K].
// mma.m16n8k16 f32 accum. Block 128x128x32, 256 threads (8 warps 2x4), warp 64x32.
#define TBM 128
#define TBN 128
#define TBK 32
#define A_LDH 40                          // halves per row (pad 8)
#define HASZ (TBM * A_LDH)                // 5120 halves
#define HBSZ (TBN * A_LDH)                // 5120 halves
#define HSTG (HASZ + HBSZ)                // 10240 halves
#define HGEMM_SMEM (2 * HSTG * 2)         // 40960 B

__device__ __forceinline__ void cph16(__half* dst_s, const __half* src_g, int sz) {
    unsigned int d = (unsigned int)__cvta_generic_to_shared(dst_s);
    asm volatile("cp.async.ca.shared.global [%0], [%1], 16, %2;\n"
                 :: "r"(d), "l"(src_g), "r"(sz));
}

__device__ __forceinline__ void hload_tiles(__half* As, __half* Bs,
                                            const __half* __restrict__ A,
                                            const __half* __restrict__ BT,
                                            int N, int K, int row0, int col0, int k0, int tid) {
#pragma unroll
    for (int it = 0; it < 2; it++) {        // A: 128 rows x 4 chunks(8 halves)
        int idx = it * 256 + tid;
        int r = idx >> 2;
        int c = (idx & 3) << 3;
        cph16(As + r * A_LDH + c, A + (size_t)(row0 + r) * K + k0 + c, 16);
    }
#pragma unroll
    for (int it = 0; it < 2; it++) {        // B: 128 n-rows x 4 chunks
        int idx = it * 256 + tid;
        int r = idx >> 2;
        int c = (idx & 3) << 3;
        int n = col0 + r;
        int sz = (n < N) ? 16 : 0;
        cph16(Bs + r * A_LDH + c, BT + (size_t)(n < N ? n : 0) * K + k0 + c, sz);
    }
    asm volatile("cp.async.commit_group;\n");
}

__device__ __forceinline__ void mma_f16(float* d, const unsigned* a, const unsigned* b) {
    asm volatile("mma.sync.aligned.m16n8k16.row.col.f32.f16.f16.f32 "
                 "{%0,%1,%2,%3}, {%4,%5,%6,%7}, {%8,%9}, {%0,%1,%2,%3};\n"
                 : "+f"(d[0]), "+f"(d[1]), "+f"(d[2]), "+f"(d[3])
                 : "r"(a[0]), "r"(a[1]), "r"(a[2]), "r"(a[3]), "r"(b[0]), "r"(b[1]));
}

template<bool OUT_HALF>
__global__ __launch_bounds__(256)
void gemm_f16(const __half* __restrict__ A, const __half* __restrict__ BT,
              const float* __restrict__ bias, void* __restrict__ Cout,
              int M, int N, int K) {
    extern __shared__ __half hsm[];
    int tid  = threadIdx.x;
    int lane = tid & 31;
    int wid  = tid >> 5;
    int g    = lane >> 2;       // 0..7
    int tig  = lane & 3;        // 0..3
    int wm   = wid >> 2;        // 0..1
    int wn   = wid & 3;         // 0..3
    int row0 = blockIdx.y * TBM;
    int col0 = blockIdx.x * TBN;

    float acc[4][4][4];
#pragma unroll
    for (int mi = 0; mi < 4; mi++)
#pragma unroll
        for (int ni = 0; ni < 4; ni++)
#pragma unroll
            for (int e = 0; e < 4; e++) acc[mi][ni][e] = 0.f;

    int nk = K / TBK;
    hload_tiles(hsm, hsm + HASZ, A, BT, N, K, row0, col0, 0, tid);

    for (int kt = 0; kt < nk; kt++) {
        asm volatile("cp.async.wait_group 0;\n");
        __syncthreads();
        if (kt + 1 < nk) {
            int st = (kt + 1) & 1;
            hload_tiles(hsm + st * HSTG, hsm + st * HSTG + HASZ,
                        A, BT, N, K, row0, col0, (kt + 1) * TBK, tid);
        }
        const __half* As = hsm + (kt & 1) * HSTG;
        const __half* Bs = As + HASZ;

#pragma unroll
        for (int ks = 0; ks < 2; ks++) {    // two k=16 steps per 32-k tile
            unsigned af[4][4];
#pragma unroll
            for (int mi = 0; mi < 4; mi++) {
                const __half* ap = As + (wm * 64 + mi * 16 + g) * A_LDH + ks * 16 + 2 * tig;
                af[mi][0] = *(const unsigned*)(ap);
                af[mi][1] = *(const unsigned*)(ap + 8 * A_LDH);
                af[mi][2] = *(const unsigned*)(ap + 8);
                af[mi][3] = *(const unsigned*)(ap + 8 * A_LDH + 8);
            }
            unsigned bf[4][2];
#pragma unroll
            for (int ni = 0; ni < 4; ni++) {
                const __half* bp = Bs + (wn * 32 + ni * 8 + g) * A_LDH + ks * 16 + 2 * tig;
                bf[ni][0] = *(const unsigned*)(bp);
                bf[ni][1] = *(const unsigned*)(bp + 8);
            }
#pragma unroll
            for (int mi = 0; mi < 4; mi++)
#pragma unroll
                for (int ni = 0; ni < 4; ni++)
                    mma_f16(acc[mi][ni], af[mi], bf[ni]);
        }
        __syncthreads();
    }

    // epilogue: bias + store (fp32 or fp16)
    float bc[4][2];
#pragma unroll
    for (int ni = 0; ni < 4; ni++) {
        int c = col0 + wn * 32 + ni * 8 + 2 * tig;
        bc[ni][0] = (c < N) ? bias[c] : 0.f;
        bc[ni][1] = (c < N) ? bias[c + 1] : 0.f;
    }
#pragma unroll
    for (int mi = 0; mi < 4; mi++) {
        int r = row0 + wm * 64 + mi * 16 + g;
#pragma unroll
        for (int ni = 0; ni < 4; ni++) {
            int c = col0 + wn * 32 + ni * 8 + 2 * tig;
            if (c < N) {
                float v00 = acc[mi][ni][0] + bc[ni][0];
                float v01 = acc[mi][ni][1] + bc[ni][1];
                float v10 = acc[mi][ni][2] + bc[ni][0];
                float v11 = acc[mi][ni][3] + bc[ni][1];
                if (OUT_HALF) {
                    __half* C = (__half*)Cout;
                    __half2 h0 = __floats2half2_rn(v00, v01);
                    __half2 h1 = __floats2half2_rn(v10, v11);
                    *(unsigned*)(C + (size_t)r * N + c)       = *(unsigned*)&h0;
                    *(unsigned*)(C + (size_t)(r + 8) * N + c) = *(unsigned*)&h1;
                } else {
                    float* C = (float*)Cout;
                    *(float2*)(C + (size_t)r * N + c)       = make_float2(v00, v01);
                    *(float2*)(C + (size_t)(r + 8) * N + c) = make_float2(v10, v11);
                }
            }
        }
    }
}

// ---------------- deformable bilinear sampling (fp16 value, 4 ch/thread) ----------------
__global__ __launch_bounds__(256)
void sample_kernel(const float* __restrict__ refp) {
    int t  = threadIdx.x;
    int q  = blockIdx.x * 4 + (t >> 6);
    int h  = (t >> 3) & 7;
    int ci = (t & 7) << 2;
    int b  = q >> 13;            // q / LQ_

    const float* oa = g_offattn + (size_t)q * 96;
    float rx = refp[q * 2 + 0];
    float ry = refp[q * 2 + 1];

    float a0 = oa[64 + h * 4 + 0];
    float a1 = oa[64 + h * 4 + 1];
    float a2 = oa[64 + h * 4 + 2];
    float a3 = oa[64 + h * 4 + 3];
    float mx = fmaxf(fmaxf(a0, a1), fmaxf(a2, a3));
    float e0 = expf(a0 - mx), e1 = expf(a1 - mx), e2 = expf(a2 - mx), e3 = expf(a3 - mx);
    float inv = 1.f / (e0 + e1 + e2 + e3);
    float aw[4] = {e0 * inv, e1 * inv, e2 * inv, e3 * inv};

    const __half* vb = (const __half*)g_value_raw + (size_t)b * S_ * D_ + h * DH_ + ci;
    float4 acc = make_float4(0.f, 0.f, 0.f, 0.f);

#pragma unroll
    for (int p = 0; p < NP_; p++) {
        float ox = oa[h * 8 + p * 2 + 0];
        float oy = oa[h * 8 + p * 2 + 1];
        float xf = rx * (float)WW_ + ox - 0.5f;
        float yf = ry * (float)HH_ + oy - 0.5f;
        float x0f = floorf(xf), y0f = floorf(yf);
        int x0 = (int)x0f, y0 = (int)y0f;
        float wx1 = xf - x0f, wy1 = yf - y0f;
        float wx0 = 1.f - wx1, wy0 = 1.f - wy1;
        float w00 = wy0 * wx0 * aw[p];
        float w01 = wy0 * wx1 * aw[p];
        float w10 = wy1 * wx0 * aw[p];
        float w11 = wy1 * wx1 * aw[p];
        int x1 = x0 + 1, y1 = y0 + 1;
        bool xin0 = (unsigned)x0 < (unsigned)WW_;
        bool xin1 = (unsigned)x1 < (unsigned)WW_;

#define GATHER(W, Y, X)                                                          \
        {                                                                        \
            uint2 raw = *(const uint2*)(vb + (size_t)((Y) * WW_ + (X)) * D_);    \
            float2 lo = __half22float2(*(__half2*)&raw.x);                       \
            float2 hi = __half22float2(*(__half2*)&raw.y);                       \
            acc.x += (W) * lo.x; acc.y += (W) * lo.y;                            \
            acc.z += (W) * hi.x; acc.w += (W) * hi.y;                            \
        }
        if ((unsigned)y0 < (unsigned)HH_) {
            if (xin0) GATHER(w00, y0, x0);
            if (xin1) GATHER(w01, y0, x1);
        }
        if ((unsigned)y1 < (unsigned)HH_) {
            if (xin0) GATHER(w10, y1, x0);
            if (xin1) GATHER(w11, y1, x1);
        }
#undef GATHER
    }
    __half2 h0 = __floats2half2_rn(acc.x, acc.y);
    __half2 h1 = __floats2half2_rn(acc.z, acc.w);
    *(uint2*)((__half*)g_sampled_raw + (size_t)q * D_ + h * DH_ + ci) =
        make_uint2(*(unsigned*)&h0, *(unsigned*)&h1);
}

// ---------------- fused residual + LayerNorm over 256-wide rows ----------------
__global__ __launch_bounds__(256)
void ln_fused(const float* __restrict__ A, const float* __restrict__ Bp,
              const float* __restrict__ g, const float* __restrict__ bb,
              float* __restrict__ out, int rows) {
    int w = (blockIdx.x * blockDim.x + threadIdx.x) >> 5;
    if (w >= rows) return;
    int lane = threadIdx.x & 31;

    const float4* A4 = (const float4*)A + (size_t)w * 64;
    const float4* B4 = (const float4*)Bp + (size_t)w * 64;

    float4 xa = A4[lane];
    float4 xb = B4[lane];
    float4 ya = A4[lane + 32];
    float4 yb = B4[lane + 32];
    float4 x = make_float4(xa.x + xb.x, xa.y + xb.y, xa.z + xb.z, xa.w + xb.w);
    float4 y = make_float4(ya.x + yb.x, ya.y + yb.y, ya.z + yb.z, ya.w + yb.w);

    float s  = x.x + x.y + x.z + x.w + y.x + y.y + y.z + y.w;
    float ss = x.x * x.x + x.y * x.y + x.z * x.z + x.w * x.w
             + y.x * y.x + y.y * y.y + y.z * y.z + y.w * y.w;
#pragma unroll
    for (int o = 16; o > 0; o >>= 1) {
        s  += __shfl_xor_sync(0xffffffffu, s, o);
        ss += __shfl_xor_sync(0xffffffffu, ss, o);
    }
    float m   = s * (1.f / 256.f);
    float var = ss * (1.f / 256.f) - m * m;
    float rs  = rsqrtf(var + 1e-5f);

    const float4* g4 = (const float4*)g;
    const float4* b4 = (const float4*)bb;
    float4 g0 = g4[lane], g1 = g4[lane + 32];
    float4 c0 = b4[lane], c1 = b4[lane + 32];

    float4 o0, o1;
    o0.x = (x.x - m) * rs * g0.x + c0.x;
    o0.y = (x.y - m) * rs * g0.y + c0.y;
    o0.z = (x.z - m) * rs * g0.z + c0.z;
    o0.w = (x.w - m) * rs * g0.w + c0.w;
    o1.x = (y.x - m) * rs * g1.x + c1.x;
    o1.y = (y.y - m) * rs * g1.y + c1.y;
    o1.z = (y.z - m) * rs * g1.z + c1.z;
    o1.w = (y.w - m) * rs * g1.w + c1.w;

    float4* O4 = (float4*)out + (size_t)w * 64;
    O4[lane]      = o0;
    O4[lane + 32] = o1;
}

// ---------------- LN(2*src): reads src ONCE ----------------
__global__ __launch_bounds__(256)
void ln2_kernel(const float* __restrict__ A,
                const float* __restrict__ g, const float* __restrict__ bb,
                float* __restrict__ out, int rows) {
    int w = (blockIdx.x * blockDim.x + threadIdx.x) >> 5;
    if (w >= rows) return;
    int lane = threadIdx.x & 31;

    const float4* A4 = (const float4*)A + (size_t)w * 64;
    float4 xa = A4[lane];
    float4 ya = A4[lane + 32];
    float4 x = make_float4(2.f * xa.x, 2.f * xa.y, 2.f * xa.z, 2.f * xa.w);
    float4 y = make_float4(2.f * ya.x, 2.f * ya.y, 2.f * ya.z, 2.f * ya.w);

    float s  = x.x + x.y + x.z + x.w + y.x + y.y + y.z + y.w;
    float ss = x.x * x.x + x.y * x.y + x.z * x.z + x.w * x.w
             + y.x * y.x + y.y * y.y + y.z * y.z + y.w * y.w;
#pragma unroll
    for (int o = 16; o > 0; o >>= 1) {
        s  += __shfl_xor_sync(0xffffffffu, s, o);
        ss += __shfl_xor_sync(0xffffffffu, ss, o);
    }
    float m   = s * (1.f / 256.f);
    float var = ss * (1.f / 256.f) - m * m;
    float rs  = rsqrtf(var + 1e-5f);

    const float4* g4 = (const float4*)g;
    const float4* b4 = (const float4*)bb;
    float4 g0 = g4[lane], g1 = g4[lane + 32];
    float4 c0 = b4[lane], c1 = b4[lane + 32];

    float4 o0, o1;
    o0.x = (x.x - m) * rs * g0.x + c0.x;
    o0.y = (x.y - m) * rs * g0.y + c0.y;
    o0.z = (x.z - m) * rs * g0.z + c0.z;
    o0.w = (x.w - m) * rs * g0.w + c0.w;
    o1.x = (y.x - m) * rs * g1.x + c1.x;
    o1.y = (y.y - m) * rs * g1.y + c1.y;
    o1.z = (y.z - m) * rs * g1.z + c1.z;
    o1.w = (y.w - m) * rs * g1.w + c1.w;

    float4* O4 = (float4*)out + (size_t)w * 64;
    O4[lane]      = o0;
    O4[lane + 32] = o1;
}

// ---------------- launch ----------------
extern "C" void kernel_launch(void* const* d_in, const int* in_sizes, int n_in,
                              void* d_out, int out_size) {
    const float* tgt    = (const float*)d_in[0];
    const float* src    = (const float*)d_in[1];
    const float* refp   = (const float*)d_in[2];
    const float* Wv     = (const float*)d_in[3];
    const float* bv     = (const float*)d_in[4];
    const float* Woff   = (const float*)d_in[5];
    const float* boff   = (const float*)d_in[6];
    const float* Wattn  = (const float*)d_in[7];
    const float* battn  = (const float*)d_in[8];
    const float* Wout   = (const float*)d_in[9];
    const float* bout   = (const float*)d_in[10];
    const float* ln1g   = (const float*)d_in[11];
    const float* ln1b   = (const float*)d_in[12];
    const float* ln2g   = (const float*)d_in[13];
    const float* ln2b   = (const float*)d_in[14];

    float* out = (float*)d_out;

    void *p_srch, *p_tgth, *p_value, *p_sampled, *p_WvT, *p_WoutT, *p_WoaT;
    float *p_offattn, *p_attnout, *p_boa;
    cudaGetSymbolAddress(&p_srch,    g_srch_raw);
    cudaGetSymbolAddress(&p_tgth,    g_tgth_raw);
    cudaGetSymbolAddress(&p_value,   g_value_raw);
    cudaGetSymbolAddress(&p_sampled, g_sampled_raw);
    cudaGetSymbolAddress(&p_WvT,     g_WvT_raw);
    cudaGetSymbolAddress(&p_WoutT,   g_WoutT_raw);
    cudaGetSymbolAddress(&p_WoaT,    g_WoaT_raw);
    cudaGetSymbolAddress((void**)&p_offattn, g_offattn);
    cudaGetSymbolAddress((void**)&p_attnout, g_attnout);
    cudaGetSymbolAddress((void**)&p_boa,     g_boa);

    cudaFuncSetAttribute(gemm_f16<false>, cudaFuncAttributeMaxDynamicSharedMemorySize,
                         HGEMM_SMEM);
    cudaFuncSetAttribute(gemm_f16<true>, cudaFuncAttributeMaxDynamicSharedMemorySize,
                         HGEMM_SMEM);

    // 0) pack/transpose weights to fp16
    pack_wT_kernel<<<(256 * 256 + 255) / 256, 256>>>(Wv, Wout, Woff, boff, Wattn, battn);

    // 0b) convert activations to fp16
    cvt_f2h<<<(NS_ * D_ / 4 + 255) / 256, 256>>>(src, (__half*)p_srch, NS_ * D_ / 4);
    cvt_f2h<<<(NQ_ * D_ / 4 + 255) / 256, 256>>>(tgt, (__half*)p_tgth, NQ_ * D_ / 4);

    // 1) value = src @ Wv + bv -> fp16 [65536,256]
    {
        dim3 grid(D_ / TBN, NS_ / TBM);
        gemm_f16<true><<<grid, 256, HGEMM_SMEM>>>((const __half*)p_srch, (const __half*)p_WvT,
                                                  bv, p_value, NS_, D_, D_);
    }

    // 2) off|attn = tgt @ Woa + boa -> fp32 [32768,96]
    {
        dim3 grid(1, NQ_ / TBM);
        gemm_f16<false><<<grid, 256, HGEMM_SMEM>>>((const __half*)p_tgth, (const __half*)p_WoaT,
                                                   p_boa, p_offattn, NQ_, 96, D_);
    }

    // 3) deformable sampling -> fp16 sampled [32768,256]
    sample_kernel<<<NQ_ / 4, 256>>>(refp);

    // 4) attn_out = sampled @ Wout + bout -> fp32 [32768,256]
    {
        dim3 grid(D_ / TBN, NQ_ / TBM);
        gemm_f16<false><<<grid, 256, HGEMM_SMEM>>>((const __half*)p_sampled, (const __half*)p_WoutT,
                                                   bout, p_attnout, NQ_, D_, D_);
    }

    // 5) query = LN(tgt + attn_out) -> out[0 : NQ*D]
    ln_fused<<<(NQ_ * 32 + 255) / 256, 256>>>(tgt, p_attnout, ln1g, ln1b, out, NQ_);

    // 6) src_out = LN(2*src) -> out[NQ*D : ...]
    ln2_kernel<<<(NS_ * 32 + 255) / 256, 256>>>(src, ln2g, ln2b, out + (size_t)NQ_ * D_, NS_);
}

// round 11
// speedup vs baseline: 1.6330x; 1.0358x over previous
#include <cuda_runtime.h>
#include <cuda_fp16.h>
#include <cstdint>
#include <math.h>

// Problem constants
#define B_   4
#define LQ_  8192
#define S_   16384
#define D_   256
#define NH_  8
#define NP_  4
#define DH_  32
#define HH_  128
#define WW_  128
#define NQ_  (B_ * LQ_)   // 32768
#define NS_  (B_ * S_)    // 65536

// ---------------- scratch (static __device__, 16B-aligned via uint4) ----------------
__device__ uint4 g_srch_raw[(size_t)NS_ * D_ / 8];      // src fp16, 32 MB
__device__ uint4 g_tgth_raw[(size_t)NQ_ * D_ / 8];      // tgt fp16, 16 MB
__device__ uint4 g_value_raw[(size_t)NS_ * D_ / 8];     // value fp16, 32 MB
__device__ uint4 g_sampled_raw[(size_t)NQ_ * D_ / 8];   // sampled fp16, 16 MB
__device__ float g_offattn[(size_t)NQ_ * 96];           // fp32, 12 MB
__device__ float g_attnout[(size_t)NQ_ * D_];           // fp32, 32 MB
__device__ uint4 g_WvT_raw[256 * 256 / 8];              // Wv^T fp16 [N][K]
__device__ uint4 g_WoutT_raw[256 * 256 / 8];            // Wout^T fp16 [N][K]
__device__ uint4 g_WoaT_raw[96 * 256 / 8];              // [Woff|Wattn]^T fp16 [96][K]
__device__ float g_boa[96];

// ---------------- fp32 -> fp16 convert (vectorized) ----------------
__global__ void cvt_f2h(const float* __restrict__ in, __half* __restrict__ outp, int n4) {
    int i = blockIdx.x * blockDim.x + threadIdx.x;
    if (i >= n4) return;
    float4 v = ((const float4*)in)[i];
    __half2 lo = __floats2half2_rn(v.x, v.y);
    __half2 hi = __floats2half2_rn(v.z, v.w);
    ((uint2*)outp)[i] = make_uint2(*(unsigned*)&lo, *(unsigned*)&hi);
}

// ---------------- pack + transpose weights to fp16 [N][K] ----------------
__global__ void pack_wT_kernel(const float* __restrict__ Wv, const float* __restrict__ Wout,
                               const float* __restrict__ Woff, const float* __restrict__ boff,
                               const float* __restrict__ Wattn, const float* __restrict__ battn) {
    int i = blockIdx.x * blockDim.x + threadIdx.x;   // over 256*256
    if (i < 256 * 256) {
        int n = i / 256, k = i % 256;
        ((__half*)g_WvT_raw)[n * 256 + k]   = __float2half_rn(Wv[k * 256 + n]);
        ((__half*)g_WoutT_raw)[n * 256 + k] = __float2half_rn(Wout[k * 256 + n]);
        if (n < 96) {
            float w = (n < 64) ? Woff[k * 64 + n] : Wattn[k * 32 + (n - 64)];
            ((__half*)g_WoaT_raw)[n * 256 + k] = __float2half_rn(w);
        }
    }
    if (i < 96) g_boa[i] = (i < 64) ? boff[i] : battn[i - 64];
}

// ================= fp16 tensor-core GEMM (ldmatrix fragments) =================
// C[M,N] = A[M,K] @ BT[N,K]^T + bias. A fp16 row-major, BT fp16 [N][K].
// mma.m16n8k16 f32 accum. Block 128x128x32, 256 threads (8 warps 2x4), warp 64x32.
#define TBM 128
#define TBN 128
#define TBK 32
#define A_LDH 40                          // halves per row (pad 8) -> 80B row stride
#define HASZ (TBM * A_LDH)                // 5120 halves
#define HBSZ (TBN * A_LDH)                // 5120 halves
#define HSTG (HASZ + HBSZ)                // 10240 halves
#define HGEMM_SMEM (2 * HSTG * 2)         // 40960 B

__device__ __forceinline__ void cph16(__half* dst_s, const __half* src_g, int sz) {
    unsigned int d = (unsigned int)__cvta_generic_to_shared(dst_s);
    asm volatile("cp.async.ca.shared.global [%0], [%1], 16, %2;\n"
                 :: "r"(d), "l"(src_g), "r"(sz));
}

__device__ __forceinline__ void hload_tiles(__half* As, __half* Bs,
                                            const __half* __restrict__ A,
                                            const __half* __restrict__ BT,
                                            int N, int K, int row0, int col0, int k0, int tid) {
#pragma unroll
    for (int it = 0; it < 2; it++) {        // A: 128 rows x 4 chunks(8 halves)
        int idx = it * 256 + tid;
        int r = idx >> 2;
        int c = (idx & 3) << 3;
        cph16(As + r * A_LDH + c, A + (size_t)(row0 + r) * K + k0 + c, 16);
    }
#pragma unroll
    for (int it = 0; it < 2; it++) {        // B: 128 n-rows x 4 chunks
        int idx = it * 256 + tid;
        int r = idx >> 2;
        int c = (idx & 3) << 3;
        int n = col0 + r;
        int sz = (n < N) ? 16 : 0;
        cph16(Bs + r * A_LDH + c, BT + (size_t)(n < N ? n : 0) * K + k0 + c, sz);
    }
    asm volatile("cp.async.commit_group;\n");
}

__device__ __forceinline__ void ldsm4(unsigned& r0, unsigned& r1, unsigned& r2, unsigned& r3,
                                      unsigned addr) {
    asm volatile("ldmatrix.sync.aligned.m8n8.x4.shared.b16 {%0,%1,%2,%3}, [%4];"
                 : "=r"(r0), "=r"(r1), "=r"(r2), "=r"(r3) : "r"(addr));
}

__device__ __forceinline__ void mma_f16(float* d, const unsigned* a, const unsigned* b) {
    asm volatile("mma.sync.aligned.m16n8k16.row.col.f32.f16.f16.f32 "
                 "{%0,%1,%2,%3}, {%4,%5,%6,%7}, {%8,%9}, {%0,%1,%2,%3};\n"
                 : "+f"(d[0]), "+f"(d[1]), "+f"(d[2]), "+f"(d[3])
                 : "r"(a[0]), "r"(a[1]), "r"(a[2]), "r"(a[3]), "r"(b[0]), "r"(b[1]));
}

template<bool OUT_HALF>
__global__ __launch_bounds__(256)
void gemm_f16(const __half* __restrict__ A, const __half* __restrict__ BT,
              const float* __restrict__ bias, void* __restrict__ Cout,
              int M, int N, int K) {
    extern __shared__ __half hsm[];
    int tid  = threadIdx.x;
    int lane = tid & 31;
    int wid  = tid >> 5;
    int g    = lane >> 2;       // 0..7
    int tig  = lane & 3;        // 0..3
    int wm   = wid >> 2;        // 0..1
    int wn   = wid & 3;         // 0..3
    int row0 = blockIdx.y * TBM;
    int col0 = blockIdx.x * TBN;

    // per-lane ldmatrix row/col offsets (x4: matrix i <- lanes 8i..8i+7)
    // A: M0 rows0-7 k0 | M1 rows8-15 k0 | M2 rows0-7 k8 | M3 rows8-15 k8
    int a_row = wm * 64 + (lane & 15);            // + mi*16
    int a_col = (lane >> 4) << 3;                 // + ks*16
    // B: M0 n0-7 k0 | M1 n0-7 k8 | M2 n8-15 k0 | M3 n8-15 k8  (per 16-n group)
    int b_row = wn * 32 + ((lane & 16) >> 1) + (lane & 7);   // + p*16
    int b_col = (lane & 8);                       // 0 or 8, + ks*16

    unsigned smem_u32 = (unsigned)__cvta_generic_to_shared(hsm);

    float acc[4][4][4];
#pragma unroll
    for (int mi = 0; mi < 4; mi++)
#pragma unroll
        for (int ni = 0; ni < 4; ni++)
#pragma unroll
            for (int e = 0; e < 4; e++) acc[mi][ni][e] = 0.f;

    int nk = K / TBK;
    hload_tiles(hsm, hsm + HASZ, A, BT, N, K, row0, col0, 0, tid);

    for (int kt = 0; kt < nk; kt++) {
        asm volatile("cp.async.wait_group 0;\n");
        __syncthreads();
        if (kt + 1 < nk) {
            int st = (kt + 1) & 1;
            hload_tiles(hsm + st * HSTG, hsm + st * HSTG + HASZ,
                        A, BT, N, K, row0, col0, (kt + 1) * TBK, tid);
        }
        unsigned a_st = smem_u32 + (kt & 1) * (HSTG * 2);
        unsigned b_st = a_st + HASZ * 2;

#pragma unroll
        for (int ks = 0; ks < 2; ks++) {    // two k=16 steps per 32-k tile
            unsigned af[4][4];
#pragma unroll
            for (int mi = 0; mi < 4; mi++) {
                unsigned addr = a_st + (unsigned)(((a_row + mi * 16) * A_LDH
                                                  + a_col + ks * 16) * 2);
                ldsm4(af[mi][0], af[mi][1], af[mi][2], af[mi][3], addr);
            }
            unsigned bf[4][2];
#pragma unroll
            for (int p = 0; p < 2; p++) {
                unsigned addr = b_st + (unsigned)(((b_row + p * 16) * A_LDH
                                                  + b_col + ks * 16) * 2);
                ldsm4(bf[2 * p][0], bf[2 * p][1], bf[2 * p + 1][0], bf[2 * p + 1][1], addr);
            }
#pragma unroll
            for (int mi = 0; mi < 4; mi++)
#pragma unroll
                for (int ni = 0; ni < 4; ni++)
                    mma_f16(acc[mi][ni], af[mi], bf[ni]);
        }
        __syncthreads();
    }

    // epilogue: bias + store (fp32 or fp16)
    float bc[4][2];
#pragma unroll
    for (int ni = 0; ni < 4; ni++) {
        int c = col0 + wn * 32 + ni * 8 + 2 * tig;
        bc[ni][0] = (c < N) ? bias[c] : 0.f;
        bc[ni][1] = (c < N) ? bias[c + 1] : 0.f;
    }
#pragma unroll
    for (int mi = 0; mi < 4; mi++) {
        int r = row0 + wm * 64 + mi * 16 + g;
#pragma unroll
        for (int ni = 0; ni < 4; ni++) {
            int c = col0 + wn * 32 + ni * 8 + 2 * tig;
            if (c < N) {
                float v00 = acc[mi][ni][0] + bc[ni][0];
                float v01 = acc[mi][ni][1] + bc[ni][1];
                float v10 = acc[mi][ni][2] + bc[ni][0];
                float v11 = acc[mi][ni][3] + bc[ni][1];
                if (OUT_HALF) {
                    __half* C = (__half*)Cout;
                    __half2 h0 = __floats2half2_rn(v00, v01);
                    __half2 h1 = __floats2half2_rn(v10, v11);
                    *(unsigned*)(C + (size_t)r * N + c)       = *(unsigned*)&h0;
                    *(unsigned*)(C + (size_t)(r + 8) * N + c) = *(unsigned*)&h1;
                } else {
                    float* C = (float*)Cout;
                    *(float2*)(C + (size_t)r * N + c)       = make_float2(v00, v01);
                    *(float2*)(C + (size_t)(r + 8) * N + c) = make_float2(v10, v11);
                }
            }
        }
    }
}

// ---------------- deformable bilinear sampling (fp16 value, 4 ch/thread) ----------------
__global__ __launch_bounds__(256)
void sample_kernel(const float* __restrict__ refp) {
    int t  = threadIdx.x;
    int q  = blockIdx.x * 4 + (t >> 6);
    int h  = (t >> 3) & 7;
    int ci = (t & 7) << 2;
    int b  = q >> 13;            // q / LQ_

    const float* oa = g_offattn + (size_t)q * 96;
    float rx = refp[q * 2 + 0];
    float ry = refp[q * 2 + 1];

    float a0 = oa[64 + h * 4 + 0];
    float a1 = oa[64 + h * 4 + 1];
    float a2 = oa[64 + h * 4 + 2];
    float a3 = oa[64 + h * 4 + 3];
    float mx = fmaxf(fmaxf(a0, a1), fmaxf(a2, a3));
    float e0 = expf(a0 - mx), e1 = expf(a1 - mx), e2 = expf(a2 - mx), e3 = expf(a3 - mx);
    float inv = 1.f / (e0 + e1 + e2 + e3);
    float aw[4] = {e0 * inv, e1 * inv, e2 * inv, e3 * inv};

    const __half* vb = (const __half*)g_value_raw + (size_t)b * S_ * D_ + h * DH_ + ci;
    float4 acc = make_float4(0.f, 0.f, 0.f, 0.f);

#pragma unroll
    for (int p = 0; p < NP_; p++) {
        float ox = oa[h * 8 + p * 2 + 0];
        float oy = oa[h * 8 + p * 2 + 1];
        float xf = rx * (float)WW_ + ox - 0.5f;
        float yf = ry * (float)HH_ + oy - 0.5f;
        float x0f = floorf(xf), y0f = floorf(yf);
        int x0 = (int)x0f, y0 = (int)y0f;
        float wx1 = xf - x0f, wy1 = yf - y0f;
        float wx0 = 1.f - wx1, wy0 = 1.f - wy1;
        float w00 = wy0 * wx0 * aw[p];
        float w01 = wy0 * wx1 * aw[p];
        float w10 = wy1 * wx0 * aw[p];
        float w11 = wy1 * wx1 * aw[p];
        int x1 = x0 + 1, y1 = y0 + 1;
        bool xin0 = (unsigned)x0 < (unsigned)WW_;
        bool xin1 = (unsigned)x1 < (unsigned)WW_;

#define GATHER(W, Y, X)                                                          \
        {                                                                        \
            uint2 raw = *(const uint2*)(vb + (size_t)((Y) * WW_ + (X)) * D_);    \
            float2 lo = __half22float2(*(__half2*)&raw.x);                       \
            float2 hi = __half22float2(*(__half2*)&raw.y);                       \
            acc.x += (W) * lo.x; acc.y += (W) * lo.y;                            \
            acc.z += (W) * hi.x; acc.w += (W) * hi.y;                            \
        }
        if ((unsigned)y0 < (unsigned)HH_) {
            if (xin0) GATHER(w00, y0, x0);
            if (xin1) GATHER(w01, y0, x1);
        }
        if ((unsigned)y1 < (unsigned)HH_) {
            if (xin0) GATHER(w10, y1, x0);
            if (xin1) GATHER(w11, y1, x1);
        }
#undef GATHER
    }
    __half2 h0 = __floats2half2_rn(acc.x, acc.y);
    __half2 h1 = __floats2half2_rn(acc.z, acc.w);
    *(uint2*)((__half*)g_sampled_raw + (size_t)q * D_ + h * DH_ + ci) =
        make_uint2(*(unsigned*)&h0, *(unsigned*)&h1);
}

// ---------------- fused residual + LayerNorm over 256-wide rows ----------------
__global__ __launch_bounds__(256)
void ln_fused(const float* __restrict__ A, const float* __restrict__ Bp,
              const float* __restrict__ g, const float* __restrict__ bb,
              float* __restrict__ out, int rows) {
    int w = (blockIdx.x * blockDim.x + threadIdx.x) >> 5;
    if (w >= rows) return;
    int lane = threadIdx.x & 31;

    const float4* A4 = (const float4*)A + (size_t)w * 64;
    const float4* B4 = (const float4*)Bp + (size_t)w * 64;

    float4 xa = A4[lane];
    float4 xb = B4[lane];
    float4 ya = A4[lane + 32];
    float4 yb = B4[lane + 32];
    float4 x = make_float4(xa.x + xb.x, xa.y + xb.y, xa.z + xb.z, xa.w + xb.w);
    float4 y = make_float4(ya.x + yb.x, ya.y + yb.y, ya.z + yb.z, ya.w + yb.w);

    float s  = x.x + x.y + x.z + x.w + y.x + y.y + y.z + y.w;
    float ss = x.x * x.x + x.y * x.y + x.z * x.z + x.w * x.w
             + y.x * y.x + y.y * y.y + y.z * y.z + y.w * y.w;
#pragma unroll
    for (int o = 16; o > 0; o >>= 1) {
        s  += __shfl_xor_sync(0xffffffffu, s, o);
        ss += __shfl_xor_sync(0xffffffffu, ss, o);
    }
    float m   = s * (1.f / 256.f);
    float var = ss * (1.f / 256.f) - m * m;
    float rs  = rsqrtf(var + 1e-5f);

    const float4* g4 = (const float4*)g;
    const float4* b4 = (const float4*)bb;
    float4 g0 = g4[lane], g1 = g4[lane + 32];
    float4 c0 = b4[lane], c1 = b4[lane + 32];

    float4 o0, o1;
    o0.x = (x.x - m) * rs * g0.x + c0.x;
    o0.y = (x.y - m) * rs * g0.y + c0.y;
    o0.z = (x.z - m) * rs * g0.z + c0.z;
    o0.w = (x.w - m) * rs * g0.w + c0.w;
    o1.x = (y.x - m) * rs * g1.x + c1.x;
    o1.y = (y.y - m) * rs * g1.y + c1.y;
    o1.z = (y.z - m) * rs * g1.z + c1.z;
    o1.w = (y.w - m) * rs * g1.w + c1.w;

    float4* O4 = (float4*)out + (size_t)w * 64;
    O4[lane]      = o0;
    O4[lane + 32] = o1;
}

// ---------------- LN(2*src): reads src ONCE ----------------
__global__ __launch_bounds__(256)
void ln2_kernel(const float* __restrict__ A,
                const float* __restrict__ g, const float* __restrict__ bb,
                float* __restrict__ out, int rows) {
    int w = (blockIdx.x * blockDim.x + threadIdx.x) >> 5;
    if (w >= rows) return;
    int lane = threadIdx.x & 31;

    const float4* A4 = (const float4*)A + (size_t)w * 64;
    float4 xa = A4[lane];
    float4 ya = A4[lane + 32];
    float4 x = make_float4(2.f * xa.x, 2.f * xa.y, 2.f * xa.z, 2.f * xa.w);
    float4 y = make_float4(2.f * ya.x, 2.f * ya.y, 2.f * ya.z, 2.f * ya.w);

    float s  = x.x + x.y + x.z + x.w + y.x + y.y + y.z + y.w;
    float ss = x.x * x.x + x.y * x.y + x.z * x.z + x.w * x.w
             + y.x * y.x + y.y * y.y + y.z * y.z + y.w * y.w;
#pragma unroll
    for (int o = 16; o > 0; o >>= 1) {
        s  += __shfl_xor_sync(0xffffffffu, s, o);
        ss += __shfl_xor_sync(0xffffffffu, ss, o);
    }
    float m   = s * (1.f / 256.f);
    float var = ss * (1.f / 256.f) - m * m;
    float rs  = rsqrtf(var + 1e-5f);

    const float4* g4 = (const float4*)g;
    const float4* b4 = (const float4*)bb;
    float4 g0 = g4[lane], g1 = g4[lane + 32];
    float4 c0 = b4[lane], c1 = b4[lane + 32];

    float4 o0, o1;
    o0.x = (x.x - m) * rs * g0.x + c0.x;
    o0.y = (x.y - m) * rs * g0.y + c0.y;
    o0.z = (x.z - m) * rs * g0.z + c0.z;
    o0.w = (x.w - m) * rs * g0.w + c0.w;
    o1.x = (y.x - m) * rs * g1.x + c1.x;
    o1.y = (y.y - m) * rs * g1.y + c1.y;
    o1.z = (y.z - m) * rs * g1.z + c1.z;
    o1.w = (y.w - m) * rs * g1.w + c1.w;

    float4* O4 = (float4*)out + (size_t)w * 64;
    O4[lane]      = o0;
    O4[lane + 32] = o1;
}

// ---------------- launch ----------------
extern "C" void kernel_launch(void* const* d_in, const int* in_sizes, int n_in,
                              void* d_out, int out_size) {
    const float* tgt    = (const float*)d_in[0];
    const float* src    = (const float*)d_in[1];
    const float* refp   = (const float*)d_in[2];
    const float* Wv     = (const float*)d_in[3];
    const float* bv     = (const float*)d_in[4];
    const float* Woff   = (const float*)d_in[5];
    const float* boff   = (const float*)d_in[6];
    const float* Wattn  = (const float*)d_in[7];
    const float* battn  = (const float*)d_in[8];
    const float* Wout   = (const float*)d_in[9];
    const float* bout   = (const float*)d_in[10];
    const float* ln1g   = (const float*)d_in[11];
    const float* ln1b   = (const float*)d_in[12];
    const float* ln2g   = (const float*)d_in[13];
    const float* ln2b   = (const float*)d_in[14];

    float* out = (float*)d_out;

    void *p_srch, *p_tgth, *p_value, *p_sampled, *p_WvT, *p_WoutT, *p_WoaT;
    float *p_offattn, *p_attnout, *p_boa;
    cudaGetSymbolAddress(&p_srch,    g_srch_raw);
    cudaGetSymbolAddress(&p_tgth,    g_tgth_raw);
    cudaGetSymbolAddress(&p_value,   g_value_raw);
    cudaGetSymbolAddress(&p_sampled, g_sampled_raw);
    cudaGetSymbolAddress(&p_WvT,     g_WvT_raw);
    cudaGetSymbolAddress(&p_WoutT,   g_WoutT_raw);
    cudaGetSymbolAddress(&p_WoaT,    g_WoaT_raw);
    cudaGetSymbolAddress((void**)&p_offattn, g_offattn);
    cudaGetSymbolAddress((void**)&p_attnout, g_attnout);
    cudaGetSymbolAddress((void**)&p_boa,     g_boa);

    cudaFuncSetAttribute(gemm_f16<false>, cudaFuncAttributeMaxDynamicSharedMemorySize,
                         HGEMM_SMEM);
    cudaFuncSetAttribute(gemm_f16<true>, cudaFuncAttributeMaxDynamicSharedMemorySize,
                         HGEMM_SMEM);

    // 0) pack/transpose weights to fp16
    pack_wT_kernel<<<(256 * 256 + 255) / 256, 256>>>(Wv, Wout, Woff, boff, Wattn, battn);

    // 0b) convert activations to fp16
    cvt_f2h<<<(NS_ * D_ / 4 + 255) / 256, 256>>>(src, (__half*)p_srch, NS_ * D_ / 4);
    cvt_f2h<<<(NQ_ * D_ / 4 + 255) / 256, 256>>>(tgt, (__half*)p_tgth, NQ_ * D_ / 4);

    // 1) value = src @ Wv + bv -> fp16 [65536,256]
    {
        dim3 grid(D_ / TBN, NS_ / TBM);
        gemm_f16<true><<<grid, 256, HGEMM_SMEM>>>((const __half*)p_srch, (const __half*)p_WvT,
                                                  bv, p_value, NS_, D_, D_);
    }

    // 2) off|attn = tgt @ Woa + boa -> fp32 [32768,96]
    {
        dim3 grid(1, NQ_ / TBM);
        gemm_f16<false><<<grid, 256, HGEMM_SMEM>>>((const __half*)p_tgth, (const __half*)p_WoaT,
                                                   p_boa, p_offattn, NQ_, 96, D_);
    }

    // 3) deformable sampling -> fp16 sampled [32768,256]
    sample_kernel<<<NQ_ / 4, 256>>>(refp);

    // 4) attn_out = sampled @ Wout + bout -> fp32 [32768,256]
    {
        dim3 grid(D_ / TBN, NQ_ / TBM);
        gemm_f16<false><<<grid, 256, HGEMM_SMEM>>>((const __half*)p_sampled, (const __half*)p_WoutT,
                                                   bout, p_attnout, NQ_, D_, D_);
    }

    // 5) query = LN(tgt + attn_out) -> out[0 : NQ*D]
    ln_fused<<<(NQ_ * 32 + 255) / 256, 256>>>(tgt, p_attnout, ln1g, ln1b, out, NQ_);

    // 6) src_out = LN(2*src) -> out[NQ*D : ...]
    ln2_kernel<<<(NS_ * 32 + 255) / 256, 256>>>(src, ln2g, ln2b, out + (size_t)NQ_ * D_, NS_);
}

// round 13
// speedup vs baseline: 1.6535x; 1.0126x over previous
#include <cuda_runtime.h>
#include <cuda_fp16.h>
#include <cstdint>
#include <math.h>

// Problem constants
#define B_   4
#define LQ_  8192
#define S_   16384
#define D_   256
#define NH_  8
#define NP_  4
#define DH_  32
#define HH_  128
#define WW_  128
#define NQ_  (B_ * LQ_)   // 32768
#define NS_  (B_ * S_)    // 65536

// ---------------- scratch (static __device__, 16B-aligned via uint4) ----------------
__device__ uint4 g_srch_raw[(size_t)NS_ * D_ / 8];      // src fp16, 32 MB
__device__ uint4 g_tgth_raw[(size_t)NQ_ * D_ / 8];      // tgt fp16, 16 MB
__device__ uint4 g_value_raw[(size_t)NS_ * D_ / 8];     // value fp16, 32 MB
__device__ uint4 g_sampled_raw[(size_t)NQ_ * D_ / 8];   // sampled fp16, 16 MB
__device__ float g_offattn[(size_t)NQ_ * 96];           // fp32, 12 MB
__device__ float g_attnout[(size_t)NQ_ * D_];           // fp32, 32 MB
__device__ uint4 g_WvT_raw[256 * 256 / 8];              // Wv^T fp16 [N][K]
__device__ uint4 g_WoutT_raw[256 * 256 / 8];            // Wout^T fp16 [N][K]
__device__ uint4 g_WoaT_raw[96 * 256 / 8];              // [Woff|Wattn]^T fp16 [96][K]
__device__ float g_boa[96];

// ---------------- fp32 -> fp16 convert (vectorized) ----------------
__global__ void cvt_f2h(const float* __restrict__ in, __half* __restrict__ outp, int n4) {
    int i = blockIdx.x * blockDim.x + threadIdx.x;
    if (i >= n4) return;
    float4 v = ((const float4*)in)[i];
    __half2 lo = __floats2half2_rn(v.x, v.y);
    __half2 hi = __floats2half2_rn(v.z, v.w);
    ((uint2*)outp)[i] = make_uint2(*(unsigned*)&lo, *(unsigned*)&hi);
}

// ---------------- pack + transpose weights to fp16 [N][K] ----------------
__global__ void pack_wT_kernel(const float* __restrict__ Wv, const float* __restrict__ Wout,
                               const float* __restrict__ Woff, const float* __restrict__ boff,
                               const float* __restrict__ Wattn, const float* __restrict__ battn) {
    int i = blockIdx.x * blockDim.x + threadIdx.x;   // over 256*256
    if (i < 256 * 256) {
        int n = i / 256, k = i % 256;
        ((__half*)g_WvT_raw)[n * 256 + k]   = __float2half_rn(Wv[k * 256 + n]);
        ((__half*)g_WoutT_raw)[n * 256 + k] = __float2half_rn(Wout[k * 256 + n]);
        if (n < 96) {
            float w = (n < 64) ? Woff[k * 64 + n] : Wattn[k * 32 + (n - 64)];
            ((__half*)g_WoaT_raw)[n * 256 + k] = __float2half_rn(w);
        }
    }
    if (i < 96) g_boa[i] = (i < 64) ? boff[i] : battn[i - 64];
}

// ================= fp16 tensor-core GEMM (ldmatrix + 3-stage cp.async) =================
// C[M,N] = A[M,K] @ BT[N,K]^T + bias. A fp16 row-major, BT fp16 [N][K].
// mma.m16n8k16 f32 accum. Block 128x128x32, 256 threads (8 warps 2x4), warp 64x32.
#define TBM 128
#define TBN 128
#define TBK 32
#define A_LDH 40                          // halves per row (pad 8) -> 80B row stride
#define HASZ (TBM * A_LDH)                // 5120 halves
#define HBSZ (TBN * A_LDH)                // 5120 halves
#define HSTG (HASZ + HBSZ)                // 10240 halves per stage
#define NSTAGE 3
#define HGEMM_SMEM (NSTAGE * HSTG * 2)    // 61440 B

__device__ __forceinline__ void cph16(__half* dst_s, const __half* src_g, int sz) {
    unsigned int d = (unsigned int)__cvta_generic_to_shared(dst_s);
    asm volatile("cp.async.ca.shared.global [%0], [%1], 16, %2;\n"
                 :: "r"(d), "l"(src_g), "r"(sz));
}

__device__ __forceinline__ void hload_tiles(__half* As, __half* Bs,
                                            const __half* __restrict__ A,
                                            const __half* __restrict__ BT,
                                            int N, int K, int row0, int col0, int k0, int tid) {
#pragma unroll
    for (int it = 0; it < 2; it++) {        // A: 128 rows x 4 chunks(8 halves)
        int idx = it * 256 + tid;
        int r = idx >> 2;
        int c = (idx & 3) << 3;
        cph16(As + r * A_LDH + c, A + (size_t)(row0 + r) * K + k0 + c, 16);
    }
#pragma unroll
    for (int it = 0; it < 2; it++) {        // B: 128 n-rows x 4 chunks
        int idx = it * 256 + tid;
        int r = idx >> 2;
        int c = (idx & 3) << 3;
        int n = col0 + r;
        int sz = (n < N) ? 16 : 0;
        cph16(Bs + r * A_LDH + c, BT + (size_t)(n < N ? n : 0) * K + k0 + c, sz);
    }
    asm volatile("cp.async.commit_group;\n");
}

__device__ __forceinline__ void ldsm4(unsigned& r0, unsigned& r1, unsigned& r2, unsigned& r3,
                                      unsigned addr) {
    asm volatile("ldmatrix.sync.aligned.m8n8.x4.shared.b16 {%0,%1,%2,%3}, [%4];"
                 : "=r"(r0), "=r"(r1), "=r"(r2), "=r"(r3) : "r"(addr));
}

__device__ __forceinline__ void mma_f16(float* d, const unsigned* a, const unsigned* b) {
    asm volatile("mma.sync.aligned.m16n8k16.row.col.f32.f16.f16.f32 "
                 "{%0,%1,%2,%3}, {%4,%5,%6,%7}, {%8,%9}, {%0,%1,%2,%3};\n"
                 : "+f"(d[0]), "+f"(d[1]), "+f"(d[2]), "+f"(d[3])
                 : "r"(a[0]), "r"(a[1]), "r"(a[2]), "r"(a[3]), "r"(b[0]), "r"(b[1]));
}

template<bool OUT_HALF>
__global__ __launch_bounds__(256)
void gemm_f16(const __half* __restrict__ A, const __half* __restrict__ BT,
              const float* __restrict__ bias, void* __restrict__ Cout,
              int M, int N, int K) {
    extern __shared__ __half hsm[];
    int tid  = threadIdx.x;
    int lane = tid & 31;
    int wid  = tid >> 5;
    int g    = lane >> 2;       // 0..7
    int tig  = lane & 3;        // 0..3
    int wm   = wid >> 2;        // 0..1
    int wn   = wid & 3;         // 0..3
    int row0 = blockIdx.y * TBM;
    int col0 = blockIdx.x * TBN;

    // per-lane ldmatrix row/col offsets (x4: matrix i <- lanes 8i..8i+7)
    int a_row = wm * 64 + (lane & 15);            // + mi*16
    int a_col = (lane >> 4) << 3;                 // + ks*16
    int b_row = wn * 32 + ((lane & 16) >> 1) + (lane & 7);   // + p*16
    int b_col = (lane & 8);                       // + ks*16

    unsigned smem_u32 = (unsigned)__cvta_generic_to_shared(hsm);

    float acc[4][4][4];
#pragma unroll
    for (int mi = 0; mi < 4; mi++)
#pragma unroll
        for (int ni = 0; ni < 4; ni++)
#pragma unroll
            for (int e = 0; e < 4; e++) acc[mi][ni][e] = 0.f;

    int nk = K / TBK;   // = 8
    // prologue: issue stages 0 and 1
    hload_tiles(hsm, hsm + HASZ, A, BT, N, K, row0, col0, 0, tid);
    hload_tiles(hsm + HSTG, hsm + HSTG + HASZ, A, BT, N, K, row0, col0, TBK, tid);

    for (int kt = 0; kt < nk; kt++) {
        asm volatile("cp.async.wait_group 1;\n");   // tile kt resident; kt+1 may be in flight
        __syncthreads();
        if (kt + 2 < nk) {
            int st = (kt + 2) % NSTAGE;             // == (kt-1)%NSTAGE, freed by the barrier above
            hload_tiles(hsm + st * HSTG, hsm + st * HSTG + HASZ,
                        A, BT, N, K, row0, col0, (kt + 2) * TBK, tid);
        }
        unsigned a_st = smem_u32 + (unsigned)((kt % NSTAGE) * (HSTG * 2));
        unsigned b_st = a_st + HASZ * 2;

#pragma unroll
        for (int ks = 0; ks < 2; ks++) {    // two k=16 steps per 32-k tile
            unsigned af[4][4];
#pragma unroll
            for (int mi = 0; mi < 4; mi++) {
                unsigned addr = a_st + (unsigned)(((a_row + mi * 16) * A_LDH
                                                  + a_col + ks * 16) * 2);
                ldsm4(af[mi][0], af[mi][1], af[mi][2], af[mi][3], addr);
            }
            unsigned bf[4][2];
#pragma unroll
            for (int p = 0; p < 2; p++) {
                unsigned addr = b_st + (unsigned)(((b_row + p * 16) * A_LDH
                                                  + b_col + ks * 16) * 2);
                ldsm4(bf[2 * p][0], bf[2 * p][1], bf[2 * p + 1][0], bf[2 * p + 1][1], addr);
            }
#pragma unroll
            for (int mi = 0; mi < 4; mi++)
#pragma unroll
                for (int ni = 0; ni < 4; ni++)
                    mma_f16(acc[mi][ni], af[mi], bf[ni]);
        }
    }

    // epilogue: bias + store (fp32 or fp16)
    float bc[4][2];
#pragma unroll
    for (int ni = 0; ni < 4; ni++) {
        int c = col0 + wn * 32 + ni * 8 + 2 * tig;
        bc[ni][0] = (c < N) ? bias[c] : 0.f;
        bc[ni][1] = (c < N) ? bias[c + 1] : 0.f;
    }
#pragma unroll
    for (int mi = 0; mi < 4; mi++) {
        int r = row0 + wm * 64 + mi * 16 + g;
#pragma unroll
        for (int ni = 0; ni < 4; ni++) {
            int c = col0 + wn * 32 + ni * 8 + 2 * tig;
            if (c < N) {
                float v00 = acc[mi][ni][0] + bc[ni][0];
                float v01 = acc[mi][ni][1] + bc[ni][1];
                float v10 = acc[mi][ni][2] + bc[ni][0];
                float v11 = acc[mi][ni][3] + bc[ni][1];
                if (OUT_HALF) {
                    __half* C = (__half*)Cout;
                    __half2 h0 = __floats2half2_rn(v00, v01);
                    __half2 h1 = __floats2half2_rn(v10, v11);
                    *(unsigned*)(C + (size_t)r * N + c)       = *(unsigned*)&h0;
                    *(unsigned*)(C + (size_t)(r + 8) * N + c) = *(unsigned*)&h1;
                } else {
                    float* C = (float*)Cout;
                    *(float2*)(C + (size_t)r * N + c)       = make_float2(v00, v01);
                    *(float2*)(C + (size_t)(r + 8) * N + c) = make_float2(v10, v11);
                }
            }
        }
    }
}

// ---------------- deformable bilinear sampling (fp16 value, 4 ch/thread) ----------------
__global__ __launch_bounds__(256)
void sample_kernel(const float* __restrict__ refp) {
    int t  = threadIdx.x;
    int q  = blockIdx.x * 4 + (t >> 6);
    int h  = (t >> 3) & 7;
    int ci = (t & 7) << 2;
    int b  = q >> 13;            // q / LQ_

    const float* oa = g_offattn + (size_t)q * 96;
    float rx = refp[q * 2 + 0];
    float ry = refp[q * 2 + 1];

    float a0 = oa[64 + h * 4 + 0];
    float a1 = oa[64 + h * 4 + 1];
    float a2 = oa[64 + h * 4 + 2];
    float a3 = oa[64 + h * 4 + 3];
    float mx = fmaxf(fmaxf(a0, a1), fmaxf(a2, a3));
    float e0 = expf(a0 - mx), e1 = expf(a1 - mx), e2 = expf(a2 - mx), e3 = expf(a3 - mx);
    float inv = 1.f / (e0 + e1 + e2 + e3);
    float aw[4] = {e0 * inv, e1 * inv, e2 * inv, e3 * inv};

    const __half* vb = (const __half*)g_value_raw + (size_t)b * S_ * D_ + h * DH_ + ci;
    float4 acc = make_float4(0.f, 0.f, 0.f, 0.f);

#pragma unroll
    for (int p = 0; p < NP_; p++) {
        float ox = oa[h * 8 + p * 2 + 0];
        float oy = oa[h * 8 + p * 2 + 1];
        float xf = rx * (float)WW_ + ox - 0.5f;
        float yf = ry * (float)HH_ + oy - 0.5f;
        float x0f = floorf(xf), y0f = floorf(yf);
        int x0 = (int)x0f, y0 = (int)y0f;
        float wx1 = xf - x0f, wy1 = yf - y0f;
        float wx0 = 1.f - wx1, wy0 = 1.f - wy1;
        float w00 = wy0 * wx0 * aw[p];
        float w01 = wy0 * wx1 * aw[p];
        float w10 = wy1 * wx0 * aw[p];
        float w11 = wy1 * wx1 * aw[p];
        int x1 = x0 + 1, y1 = y0 + 1;
        bool xin0 = (unsigned)x0 < (unsigned)WW_;
        bool xin1 = (unsigned)x1 < (unsigned)WW_;

#define GATHER(W, Y, X)                                                          \
        {                                                                        \
            uint2 raw = *(const uint2*)(vb + (size_t)((Y) * WW_ + (X)) * D_);    \
            float2 lo = __half22float2(*(__half2*)&raw.x);                       \
            float2 hi = __half22float2(*(__half2*)&raw.y);                       \
            acc.x += (W) * lo.x; acc.y += (W) * lo.y;                            \
            acc.z += (W) * hi.x; acc.w += (W) * hi.y;                            \
        }
        if ((unsigned)y0 < (unsigned)HH_) {
            if (xin0) GATHER(w00, y0, x0);
            if (xin1) GATHER(w01, y0, x1);
        }
        if ((unsigned)y1 < (unsigned)HH_) {
            if (xin0) GATHER(w10, y1, x0);
            if (xin1) GATHER(w11, y1, x1);
        }
#undef GATHER
    }
    __half2 h0 = __floats2half2_rn(acc.x, acc.y);
    __half2 h1 = __floats2half2_rn(acc.z, acc.w);
    *(uint2*)((__half*)g_sampled_raw + (size_t)q * D_ + h * DH_ + ci) =
        make_uint2(*(unsigned*)&h0, *(unsigned*)&h1);
}

// ---------------- fused residual + LayerNorm over 256-wide rows ----------------
__global__ __launch_bounds__(256)
void ln_fused(const float* __restrict__ A, const float* __restrict__ Bp,
              const float* __restrict__ g, const float* __restrict__ bb,
              float* __restrict__ out, int rows) {
    int w = (blockIdx.x * blockDim.x + threadIdx.x) >> 5;
    if (w >= rows) return;
    int lane = threadIdx.x & 31;

    const float4* A4 = (const float4*)A + (size_t)w * 64;
    const float4* B4 = (const float4*)Bp + (size_t)w * 64;

    float4 xa = A4[lane];
    float4 xb = B4[lane];
    float4 ya = A4[lane + 32];
    float4 yb = B4[lane + 32];
    float4 x = make_float4(xa.x + xb.x, xa.y + xb.y, xa.z + xb.z, xa.w + xb.w);
    float4 y = make_float4(ya.x + yb.x, ya.y + yb.y, ya.z + yb.z, ya.w + yb.w);

    float s  = x.x + x.y + x.z + x.w + y.x + y.y + y.z + y.w;
    float ss = x.x * x.x + x.y * x.y + x.z * x.z + x.w * x.w
             + y.x * y.x + y.y * y.y + y.z * y.z + y.w * y.w;
#pragma unroll
    for (int o = 16; o > 0; o >>= 1) {
        s  += __shfl_xor_sync(0xffffffffu, s, o);
        ss += __shfl_xor_sync(0xffffffffu, ss, o);
    }
    float m   = s * (1.f / 256.f);
    float var = ss * (1.f / 256.f) - m * m;
    float rs  = rsqrtf(var + 1e-5f);

    const float4* g4 = (const float4*)g;
    const float4* b4 = (const float4*)bb;
    float4 g0 = g4[lane], g1 = g4[lane + 32];
    float4 c0 = b4[lane], c1 = b4[lane + 32];

    float4 o0, o1;
    o0.x = (x.x - m) * rs * g0.x + c0.x;
    o0.y = (x.y - m) * rs * g0.y + c0.y;
    o0.z = (x.z - m) * rs * g0.z + c0.z;
    o0.w = (x.w - m) * rs * g0.w + c0.w;
    o1.x = (y.x - m) * rs * g1.x + c1.x;
    o1.y = (y.y - m) * rs * g1.y + c1.y;
    o1.z = (y.z - m) * rs * g1.z + c1.z;
    o1.w = (y.w - m) * rs * g1.w + c1.w;

    float4* O4 = (float4*)out + (size_t)w * 64;
    O4[lane]      = o0;
    O4[lane + 32] = o1;
}

// ---------------- LN(2*src): reads src ONCE ----------------
__global__ __launch_bounds__(256)
void ln2_kernel(const float* __restrict__ A,
                const float* __restrict__ g, const float* __restrict__ bb,
                float* __restrict__ out, int rows) {
    int w = (blockIdx.x * blockDim.x + threadIdx.x) >> 5;
    if (w >= rows) return;
    int lane = threadIdx.x & 31;

    const float4* A4 = (const float4*)A + (size_t)w * 64;
    float4 xa = A4[lane];
    float4 ya = A4[lane + 32];
    float4 x = make_float4(2.f * xa.x, 2.f * xa.y, 2.f * xa.z, 2.f * xa.w);
    float4 y = make_float4(2.f * ya.x, 2.f * ya.y, 2.f * ya.z, 2.f * ya.w);

    float s  = x.x + x.y + x.z + x.w + y.x + y.y + y.z + y.w;
    float ss = x.x * x.x + x.y * x.y + x.z * x.z + x.w * x.w
             + y.x * y.x + y.y * y.y + y.z * y.z + y.w * y.w;
#pragma unroll
    for (int o = 16; o > 0; o >>= 1) {
        s  += __shfl_xor_sync(0xffffffffu, s, o);
        ss += __shfl_xor_sync(0xffffffffu, ss, o);
    }
    float m   = s * (1.f / 256.f);
    float var = ss * (1.f / 256.f) - m * m;
    float rs  = rsqrtf(var + 1e-5f);

    const float4* g4 = (const float4*)g;
    const float4* b4 = (const float4*)bb;
    float4 g0 = g4[lane], g1 = g4[lane + 32];
    float4 c0 = b4[lane], c1 = b4[lane + 32];

    float4 o0, o1;
    o0.x = (x.x - m) * rs * g0.x + c0.x;
    o0.y = (x.y - m) * rs * g0.y + c0.y;
    o0.z = (x.z - m) * rs * g0.z + c0.z;
    o0.w = (x.w - m) * rs * g0.w + c0.w;
    o1.x = (y.x - m) * rs * g1.x + c1.x;
    o1.y = (y.y - m) * rs * g1.y + c1.y;
    o1.z = (y.z - m) * rs * g1.z + c1.z;
    o1.w = (y.w - m) * rs * g1.w + c1.w;

    float4* O4 = (float4*)out + (size_t)w * 64;
    O4[lane]      = o0;
    O4[lane + 32] = o1;
}

// ---------------- launch ----------------
extern "C" void kernel_launch(void* const* d_in, const int* in_sizes, int n_in,
                              void* d_out, int out_size) {
    const float* tgt    = (const float*)d_in[0];
    const float* src    = (const float*)d_in[1];
    const float* refp   = (const float*)d_in[2];
    const float* Wv     = (const float*)d_in[3];
    const float* bv     = (const float*)d_in[4];
    const float* Woff   = (const float*)d_in[5];
    const float* boff   = (const float*)d_in[6];
    const float* Wattn  = (const float*)d_in[7];
    const float* battn  = (const float*)d_in[8];
    const float* Wout   = (const float*)d_in[9];
    const float* bout   = (const float*)d_in[10];
    const float* ln1g   = (const float*)d_in[11];
    const float* ln1b   = (const float*)d_in[12];
    const float* ln2g   = (const float*)d_in[13];
    const float* ln2b   = (const float*)d_in[14];

    float* out = (float*)d_out;

    void *p_srch, *p_tgth, *p_value, *p_sampled, *p_WvT, *p_WoutT, *p_WoaT;
    float *p_offattn, *p_attnout, *p_boa;
    cudaGetSymbolAddress(&p_srch,    g_srch_raw);
    cudaGetSymbolAddress(&p_tgth,    g_tgth_raw);
    cudaGetSymbolAddress(&p_value,   g_value_raw);
    cudaGetSymbolAddress(&p_sampled, g_sampled_raw);
    cudaGetSymbolAddress(&p_WvT,     g_WvT_raw);
    cudaGetSymbolAddress(&p_WoutT,   g_WoutT_raw);
    cudaGetSymbolAddress(&p_WoaT,    g_WoaT_raw);
    cudaGetSymbolAddress((void**)&p_offattn, g_offattn);
    cudaGetSymbolAddress((void**)&p_attnout, g_attnout);
    cudaGetSymbolAddress((void**)&p_boa,     g_boa);

    cudaFuncSetAttribute(gemm_f16<false>, cudaFuncAttributeMaxDynamicSharedMemorySize,
                         HGEMM_SMEM);
    cudaFuncSetAttribute(gemm_f16<true>, cudaFuncAttributeMaxDynamicSharedMemorySize,
                         HGEMM_SMEM);

    // 0) pack/transpose weights to fp16
    pack_wT_kernel<<<(256 * 256 + 255) / 256, 256>>>(Wv, Wout, Woff, boff, Wattn, battn);

    // 0b) convert activations to fp16
    cvt_f2h<<<(NS_ * D_ / 4 + 255) / 256, 256>>>(src, (__half*)p_srch, NS_ * D_ / 4);
    cvt_f2h<<<(NQ_ * D_ / 4 + 255) / 256, 256>>>(tgt, (__half*)p_tgth, NQ_ * D_ / 4);

    // 1) value = src @ Wv + bv -> fp16 [65536,256]
    {
        dim3 grid(D_ / TBN, NS_ / TBM);
        gemm_f16<true><<<grid, 256, HGEMM_SMEM>>>((const __half*)p_srch, (const __half*)p_WvT,
                                                  bv, p_value, NS_, D_, D_);
    }

    // 2) off|attn = tgt @ Woa + boa -> fp32 [32768,96]
    {
        dim3 grid(1, NQ_ / TBM);
        gemm_f16<false><<<grid, 256, HGEMM_SMEM>>>((const __half*)p_tgth, (const __half*)p_WoaT,
                                                   p_boa, p_offattn, NQ_, 96, D_);
    }

    // 3) deformable sampling -> fp16 sampled [32768,256]
    sample_kernel<<<NQ_ / 4, 256>>>(refp);

    // 4) attn_out = sampled @ Wout + bout -> fp32 [32768,256]
    {
        dim3 grid(D_ / TBN, NQ_ / TBM);
        gemm_f16<false><<<grid, 256, HGEMM_SMEM>>>((const __half*)p_sampled, (const __half*)p_WoutT,
                                                   bout, p_attnout, NQ_, D_, D_);
    }

    // 5) query = LN(tgt + attn_out) -> out[0 : NQ*D]
    ln_fused<<<(NQ_ * 32 + 255) / 256, 256>>>(tgt, p_attnout, ln1g, ln1b, out, NQ_);

    // 6) src_out = LN(2*src) -> out[NQ*D : ...]
    ln2_kernel<<<(NS_ * 32 + 255) / 256, 256>>>(src, ln2g, ln2b, out + (size_t)NQ_ * D_, NS_);
}